// round 12
// baseline (speedup 1.0000x reference)
#include <cuda_runtime.h>
#include <cuda_fp16.h>
#include <math.h>
#include <stdint.h>
#include <stddef.h>

#define B_   128
#define DIN_ 128
#define T_   1024
#define H_   512
#define G4H_ 2048
#define OUT_ 2

// ---------------- scratch (static device allocations; no cudaMalloc) ----------------
__device__ __half g_xth [(size_t)T_ * B_ * DIN_];  // x transposed, fp16 hi
__device__ __half g_xtl [(size_t)T_ * B_ * DIN_];  // fp16 lo residual
__device__ __half g_w0h [(size_t)G4H_ * DIN_];     // Wih0 hi/lo (GEMM1, 3-product)
__device__ __half g_w0l [(size_t)G4H_ * DIN_];
__device__ __half g_wr0 [(size_t)G4H_ * H_];       // Whh0 fp16
__device__ __half g_wr1 [(size_t)G4H_ * H_];       // Whh1 fp16
__device__ __half g_wi1 [(size_t)G4H_ * H_];       // Wih1 fp16
// h ping-pong buffers: group-blocked, PRE-SWIZZLED (SW128 smem image), aligned for TMA
__device__ __align__(128) __half g_h0a [B_ * H_];
__device__ __align__(128) __half g_h0b [B_ * H_];
__device__ __align__(128) __half g_h1a [B_ * H_];
__device__ __align__(128) __half g_h1b [B_ * H_];
__device__ float g_xg [(size_t)T_ * G4H_ * B_];    // layer-0 gate preacts [t][n][b]
__device__ float g_hA [B_ * H_];                   // final h1 fp32 for fc
__device__ unsigned int g_bar[4 * 32];             // setup barrier
__device__ unsigned int g_flags[4 * 32 * 32];      // per-CTA flags: [+0]=h0, [+8]=h1

// ---------------- small helpers -----------------------------------------------------
__device__ __forceinline__ void hsplit(float v, __half& h, __half& l) {
    h = __float2half(v);
    l = __float2half(v - __half2float(h));
}
__device__ __forceinline__ uint32_t smem_u32(const void* p) {
    uint32_t a;
    asm("{ .reg .u64 t; cvta.to.shared.u64 t, %1; cvt.u32.u64 %0, t; }" : "=r"(a) : "l"(p));
    return a;
}
#define SWZ128(o) ((o) ^ (((o) >> 3) & 0x70))

__device__ __forceinline__ void ldsm_x4(uint32_t* r, uint32_t addr) {
    asm volatile("ldmatrix.sync.aligned.m8n8.x4.shared.b16 {%0,%1,%2,%3}, [%4];"
        : "=r"(r[0]), "=r"(r[1]), "=r"(r[2]), "=r"(r[3]) : "r"(addr));
}
__device__ __forceinline__ void mma16816(float* d, const uint32_t* a, const uint32_t* b) {
    asm volatile("mma.sync.aligned.m16n8k16.row.col.f32.f16.f16.f32 "
        "{%0,%1,%2,%3}, {%4,%5,%6,%7}, {%8,%9}, {%0,%1,%2,%3};"
        : "+f"(d[0]), "+f"(d[1]), "+f"(d[2]), "+f"(d[3])
        : "r"(a[0]), "r"(a[1]), "r"(a[2]), "r"(a[3]), "r"(b[0]), "r"(b[1]));
}
#define CPASYNC16(dst, src) \
    asm volatile("cp.async.cg.shared.global [%0], [%1], 16;" :: "r"(dst), "l"(src))
#define CPCOMMIT() asm volatile("cp.async.commit_group;" ::: "memory")
#define CPWAIT0()  asm volatile("cp.async.wait_group 0;" ::: "memory")
#define CPWAIT1()  asm volatile("cp.async.wait_group 1;" ::: "memory")

#define MBARRIER_INIT(addr, cnt) \
    asm volatile("mbarrier.init.shared.b64 [%0], %1;" :: "r"(addr), "r"(cnt) : "memory")
#define MBARRIER_EXPECT_TX(addr, tx) \
    asm volatile("mbarrier.arrive.expect_tx.shared.b64 _, [%0], %1;" \
                 :: "r"(addr), "r"(tx) : "memory")
#define TMA_BULK_G2S(dst, src, bytes, mbar) \
    asm volatile("cp.async.bulk.shared::cluster.global.mbarrier::complete_tx::bytes " \
                 "[%0], [%1], %2, [%3];" \
                 :: "r"(dst), "l"(src), "r"(bytes), "r"(mbar) : "memory")
__device__ __forceinline__ void mbar_wait(uint32_t addr, uint32_t parity) {
    uint32_t done = 0;
    while (!done) {
        asm volatile(
            "{\n\t.reg .pred p;\n\t"
            "mbarrier.try_wait.parity.shared.b64 p, [%1], %2, 0x989680;\n\t"
            "selp.b32 %0, 1, 0, p;\n\t}"
            : "=r"(done) : "r"(addr), "r"(parity) : "memory");
    }
}

// ---------------- setup-time barrier (atomic; used once per launch) -------------------
__device__ __forceinline__ void group_barrier(unsigned int* bar) {
    __syncthreads();
    if (threadIdx.x == 0) {
        unsigned int gen;
        asm volatile("ld.acquire.gpu.u32 %0, [%1];" : "=r"(gen) : "l"(bar + 1) : "memory");
        unsigned int arrived;
        asm volatile("atom.add.release.gpu.u32 %0, [%1], 1;"
                     : "=r"(arrived) : "l"(bar) : "memory");
        if (arrived == 31u) {
            asm volatile("st.relaxed.gpu.u32 [%0], 0;" :: "l"(bar) : "memory");
            asm volatile("red.add.release.gpu.u32 [%0], 1;" :: "l"(bar + 1) : "memory");
        } else {
            unsigned int g2;
            do {
                asm volatile("ld.acquire.gpu.u32 %0, [%1];"
                             : "=r"(g2) : "l"(bar + 1) : "memory");
            } while (g2 == gen);
        }
    }
    __syncthreads();
}

// ---------------- transpose x: (B, D, T) -> xt[t][b][d] as fp16 hi/lo ----------------
__global__ void transpose_kernel(const float* __restrict__ x) {
    __shared__ float tile[32][33];
    const int b  = blockIdx.z;
    const int t0 = blockIdx.x * 32;
    const int d0 = blockIdx.y * 32;
    const int tx = threadIdx.x, ty = threadIdx.y;
    #pragma unroll
    for (int i = 0; i < 4; ++i) {
        int d = d0 + ty + i * 8;
        tile[ty + i * 8][tx] = x[((size_t)b * DIN_ + d) * T_ + t0 + tx];
    }
    __syncthreads();
    #pragma unroll
    for (int i = 0; i < 4; ++i) {
        int t = t0 + ty + i * 8;
        float v = tile[tx][ty + i * 8];
        __half h, l;
        hsplit(v, h, l);
        size_t idx = ((size_t)t * B_ + b) * DIN_ + d0 + tx;
        g_xth[idx] = h;
        g_xtl[idx] = l;
    }
}

// ---------------- weight prep -------------------------------------------------------
__global__ void wsplit_kernel(const float* __restrict__ w,
                              __half* __restrict__ wh,
                              __half* __restrict__ wl, int n) {
    int i = blockIdx.x * blockDim.x + threadIdx.x;
    if (i < n) {
        __half h, l;
        hsplit(w[i], h, l);
        wh[i] = h;
        wl[i] = l;
    }
}
__global__ void wconv3_kernel(const float* __restrict__ a, __half* __restrict__ oa,
                              const float* __restrict__ b, __half* __restrict__ ob,
                              const float* __restrict__ c, __half* __restrict__ oc,
                              int n) {
    int i = blockIdx.x * blockDim.x + threadIdx.x;
    if (i >= n) return;
    if (blockIdx.y == 0)      oa[i] = __float2half(a[i]);
    else if (blockIdx.y == 1) ob[i] = __float2half(b[i]);
    else                      oc[i] = __float2half(c[i]);
}

// ---------------- mma.sync split-fp16 GEMM (3-product; xg0 anchor) -------------------
#define TILE_BYTES  16384
#define STAGE_BYTES (4 * TILE_BYTES)
#define GSM_TOTAL   (2 * STAGE_BYTES)

__global__ void __launch_bounds__(256, 1)
gemm_mma_kernel(const __half* __restrict__ Ah, const __half* __restrict__ Al,
                const __half* __restrict__ Bh, const __half* __restrict__ Bl,
                const float* __restrict__ bias1, const float* __restrict__ bias2,
                float* __restrict__ C, int K)
{
    extern __shared__ char smem[];
    const uint32_t sb = smem_u32(smem);
    const int tid  = threadIdx.x;
    const int lane = tid & 31;
    const int warp = tid >> 5;
    const int tile_t = blockIdx.y;
    const int n0blk  = blockIdx.x * 128;
    const int m_off = (warp & 3) * 32;
    const int n_off = (warp >> 2) * 64;

    const __half* gsrc[4] = {
        Ah + (size_t)tile_t * 128 * K, Al + (size_t)tile_t * 128 * K,
        Bh + (size_t)n0blk * K,        Bl + (size_t)n0blk * K };

    auto issue_stage = [&](int buf, int kc) {
        #pragma unroll
        for (int i = 0; i < 16; ++i) {
            int id  = tid + i * 256;
            int tl  = id >> 10;
            int rem = id & 1023;
            int row = rem >> 3;
            int ch  = rem & 7;
            const __half* src = gsrc[tl] + (size_t)row * K + kc * 64 + ch * 8;
            uint32_t dst = sb + buf * STAGE_BYTES + tl * TILE_BYTES
                         + SWZ128((uint32_t)(row * 128 + ch * 16));
            CPASYNC16(dst, src);
        }
        CPCOMMIT();
    };

    float acc[2][8][4];
    #pragma unroll
    for (int mf = 0; mf < 2; ++mf)
        #pragma unroll
        for (int nf = 0; nf < 8; ++nf)
            #pragma unroll
            for (int r = 0; r < 4; ++r) acc[mf][nf][r] = 0.f;

    const int nkc = K >> 6;
    issue_stage(0, 0);
    issue_stage(1, 1);

    const int a_row_base = (lane & 7) + ((lane >> 3) & 1) * 8;
    const int a_kh       = (lane >> 4) * 16;
    const int b_row_base = (lane & 7) + ((lane >> 4) & 1) * 8;
    const int b_kh       = ((lane >> 3) & 1) * 16;

    for (int kc = 0; kc < nkc; ++kc) {
        if (kc + 1 < nkc) { CPWAIT1(); } else { CPWAIT0(); }
        __syncthreads();

        const uint32_t st = sb + (kc & 1) * STAGE_BYTES;
        #pragma unroll
        for (int ks = 0; ks < 4; ++ks) {
            uint32_t ah[2][4], al[2][4], bh[16], bl[16];
            #pragma unroll
            for (int mf = 0; mf < 2; ++mf) {
                uint32_t off = SWZ128((uint32_t)((m_off + mf * 16 + a_row_base) * 128
                                                 + ks * 32 + a_kh));
                ldsm_x4(ah[mf], st + 0 * TILE_BYTES + off);
                ldsm_x4(al[mf], st + 1 * TILE_BYTES + off);
            }
            #pragma unroll
            for (int bf = 0; bf < 4; ++bf) {
                uint32_t off = SWZ128((uint32_t)((n_off + bf * 16 + b_row_base) * 128
                                                 + ks * 32 + b_kh));
                ldsm_x4(bh + bf * 4, st + 2 * TILE_BYTES + off);
                ldsm_x4(bl + bf * 4, st + 3 * TILE_BYTES + off);
            }
            #pragma unroll
            for (int mf = 0; mf < 2; ++mf)
                #pragma unroll
                for (int nf = 0; nf < 8; ++nf) {
                    mma16816(acc[mf][nf], ah[mf], bh + nf * 2);
                    mma16816(acc[mf][nf], ah[mf], bl + nf * 2);
                    mma16816(acc[mf][nf], al[mf], bh + nf * 2);
                }
        }
        __syncthreads();
        if (kc + 2 < nkc) issue_stage(kc & 1, kc + 2);
    }

    #pragma unroll
    for (int nf = 0; nf < 8; ++nf) {
        int n = n0blk + n_off + nf * 8 + 2 * (lane & 3);
        float bv0 = __ldg(&bias1[n])     + __ldg(&bias2[n]);
        float bv1 = __ldg(&bias1[n + 1]) + __ldg(&bias2[n + 1]);
        #pragma unroll
        for (int mf = 0; mf < 2; ++mf) {
            int b = m_off + mf * 16 + (lane >> 2);
            float* c0 = &C[((size_t)tile_t * G4H_ + n) * B_ + b];
            c0[0]       = acc[mf][nf][0] + bv0;
            c0[B_]      = acc[mf][nf][1] + bv1;
            c0[8]       = acc[mf][nf][2] + bv0;
            c0[B_ + 8]  = acc[mf][nf][3] + bv1;
        }
    }
}

// ---------------- fused dual-layer persistent LSTM recurrence ------------------------
// 128 CTAs = 4 b-groups (32 b) x 32 j-tiles (16 j). 256 threads.
// Two decoupled chains: phase A (h0 tile: Whh0@h0 + Wih1@h0) closes the h0 cycle
// early (epi0 -> publish -> flag0 -> warp0 issues next h0 TMA), overlapped with
// phase B (h1 tile: Whh1@h1) -> epi1 -> flag1 -> warp1 issues next h1 TMA.
#define LSM_W0   0                      // Whh0: 8 chunks x 8192 = 64 KB
#define LSM_W1   65536                  // Whh1: 64 KB
#define LSM_H0   131072                 // h0 tile 32 KB (init: Wih1 temp spans H0+H1)
#define LSM_H1   163840                 // h1 tile 32 KB
#define LSM_RED0 196608                 // 2 kh x 4 g x 16 m x 33 n x 4B = 16896
#define LSM_RED1 213504
#define LSM_MBA  230400                 // mbarrier A (h0)
#define LSM_MBB  230416                 // mbarrier B (h1)
#define LSM_TOTAL 230528

__device__ __forceinline__ float sigm_f(float v) {
    return __fdividef(1.f, 1.f + __expf(-v));
}
__device__ __forceinline__ float tanh_f(float v) {
    return 1.f - __fdividef(2.f, __expf(2.f * v) + 1.f);
}

__global__ void __launch_bounds__(256, 1)
lstm_fused_kernel(const float* __restrict__ xg,      // [t][n][b] (layer-0 preacts)
                  const __half* __restrict__ whh0,
                  const __half* __restrict__ whh1,
                  const __half* __restrict__ wih1,
                  const float* __restrict__ bih1,
                  const float* __restrict__ bhh1,
                  float* __restrict__ hfin)          // final fp32 h1
{
    extern __shared__ char sm[];
    const uint32_t sb = smem_u32(sm);
    float* red0 = (float*)(sm + LSM_RED0);
    float* red1 = (float*)(sm + LSM_RED1);
    const uint32_t mbA = sb + LSM_MBA;
    const uint32_t mbB = sb + LSM_MBB;

    const int tid  = threadIdx.x;
    const int lane = tid & 31;
    const int wid  = tid >> 5;
    const int grp  = blockIdx.x & 3;
    const int jt   = blockIdx.x >> 2;
    const int b0   = grp * 32;
    const int j0   = jt * 16;
    unsigned int* bar    = g_bar + grp * 32;
    unsigned int* myflag = &g_flags[(grp * 32 + jt) * 32];   // [+0]=h0, [+8]=h1

    const int mf = wid & 3;              // gate
    const int kh = wid >> 2;             // k-half
    const int a_row = mf * 16 + (lane & 7) + ((lane >> 3) & 1) * 8;
    const int a_kb  = (lane >> 4) * 16;
    const int b_row = (lane & 7) + ((lane >> 4) & 1) * 8;
    const int b_kb  = ((lane >> 3) & 1) * 16;

    // ---- stage Whh0 -> LSM_W0, Whh1 -> LSM_W1, Wih1 -> temp (LSM_H0+H1, 64 KB) ----
    #pragma unroll
    for (int i = 0; i < 16; ++i) {
        int id = tid + i * 256;           // 0..4095 16B-chunks
        int m  = id >> 6, ch = id & 63;
        int g = m >> 4, jl = m & 15;
        size_t roff = ((size_t)(g * H_ + j0 + jl)) * H_ + ch * 8;
        int c = ch >> 3, cc = ch & 7;
        uint32_t soff = c * 8192 + SWZ128((uint32_t)(m * 128 + cc * 16));
        *(uint4*)(sm + LSM_W0 + soff) = *(const uint4*)(whh0 + roff);
        *(uint4*)(sm + LSM_W1 + soff) = *(const uint4*)(whh1 + roff);
        *(uint4*)(sm + LSM_H0 + soff) = *(const uint4*)(wih1 + roff);
    }

    // ---- zero edge h buffers; reset flags; init mbarriers ----
    if (tid < 64) {
        int bl = tid >> 1, p = tid & 1;
        size_t o = (size_t)(b0 + bl) * H_ + j0 + p * 8;
        *(uint4*)&g_h0b[o] = make_uint4(0, 0, 0, 0);
        *(uint4*)&g_h1b[o] = make_uint4(0, 0, 0, 0);
    }
    if (tid == 0) {
        myflag[0] = 0;
        myflag[8] = 0;
        MBARRIER_INIT(mbA, 1u);
        MBARRIER_INIT(mbB, 1u);
    }
    __syncthreads();

    // ---- Wih1 A-fragments -> registers (persist whole kernel) ----
    uint32_t wi1f[64];
    #pragma unroll
    for (int kf = 0; kf < 16; ++kf) {
        int kfa = kh * 16 + kf;
        int c = kfa >> 2, ks = kfa & 3;
        ldsm_x4(&wi1f[kf * 4],
                sb + LSM_H0 + c * 8192 + SWZ128((uint32_t)(a_row * 128 + ks * 32 + a_kb)));
    }

    const int m_lo = lane >> 2;
    float bias_lo = __ldg(&bih1[mf * H_ + j0 + m_lo])     + __ldg(&bhh1[mf * H_ + j0 + m_lo]);
    float bias_hi = __ldg(&bih1[mf * H_ + j0 + m_lo + 8]) + __ldg(&bhh1[mf * H_ + j0 + m_lo + 8]);

    group_barrier(bar);   // setup complete (zeros + flag resets visible group-wide)

    // ---- initial TMA issues for t = 0 (h0[-1], h1[-2] zeros) ----
    if (tid == 0) {
        MBARRIER_EXPECT_TX(mbA, 32768u);
        TMA_BULK_G2S(sb + LSM_H0, (const char*)(g_h0b + (size_t)b0 * H_), 32768u, mbA);
        MBARRIER_EXPECT_TX(mbB, 32768u);
        TMA_BULK_G2S(sb + LSM_H1, (const char*)(g_h1b + (size_t)b0 * H_), 32768u, mbB);
    }

    const int eb = tid & 31;
    const int ej = tid >> 5;
    float c0a = 0.f, c0b = 0.f;   // layer-0 cell states
    float c1a = 0.f, c1b = 0.f;   // layer-1 cell states

    // pre-swizzled publish: value for (local batch eb, global k) -> group block offset
    auto swz_off = [&](int k) -> uint32_t {
        int c = k >> 6;
        int cc = (k >> 3) & 7;
        int lo = (k & 7) * 2;
        return (uint32_t)(c * 4096) + SWZ128((uint32_t)(eb * 128 + cc * 16)) + (uint32_t)lo;
    };

    for (int t = 0; t <= T_; ++t) {
        __half* w0 = (t & 1) ? g_h0b : g_h0a;   // h0[t] destination
        __half* w1 = (t & 1) ? g_h1a : g_h1b;   // h1[t-1] destination

        // ---- acc init: layer-0 from xg0[t] (kh=0), layer-1 from bias (kh=0) ----
        float acc0[4][4], acc1[4][4];
        if (kh == 0) {
            if (t < T_) {
                #pragma unroll
                for (int nf = 0; nf < 4; ++nf)
                    #pragma unroll
                    for (int q = 0; q < 4; ++q) {
                        int jl = (lane >> 2) + 8 * (q >> 1);
                        int bn = nf * 8 + 2 * (lane & 3) + (q & 1);
                        acc0[nf][q] = __ldg(&xg[((size_t)t * G4H_ + mf * H_ + j0 + jl) * B_
                                                + b0 + bn]);
                    }
            } else {
                #pragma unroll
                for (int nf = 0; nf < 4; ++nf)
                    #pragma unroll
                    for (int q = 0; q < 4; ++q) acc0[nf][q] = 0.f;
            }
            #pragma unroll
            for (int nf = 0; nf < 4; ++nf)
                #pragma unroll
                for (int q = 0; q < 4; ++q)
                    acc1[nf][q] = (q & 2) ? bias_hi : bias_lo;
        } else {
            #pragma unroll
            for (int nf = 0; nf < 4; ++nf)
                #pragma unroll
                for (int q = 0; q < 4; ++q) { acc0[nf][q] = 0.f; acc1[nf][q] = 0.f; }
        }

        // ================= PHASE A: h0 tile =================
        mbar_wait(mbA, (uint32_t)(t & 1));

        #pragma unroll
        for (int kf = 0; kf < 16; ++kf) {
            int kfa = kh * 16 + kf;
            int c = kfa >> 2, ks = kfa & 3;
            uint32_t a0[4], b0f[8];
            uint32_t arow = SWZ128((uint32_t)(a_row * 128 + ks * 32 + a_kb));
            ldsm_x4(a0, sb + LSM_W0 + c * 8192 + arow);
            #pragma unroll
            for (int nfp = 0; nfp < 2; ++nfp) {
                uint32_t bo = SWZ128((uint32_t)((nfp * 16 + b_row) * 128 + ks * 32 + b_kb));
                ldsm_x4(b0f + nfp * 4, sb + LSM_H0 + c * 4096 + bo);
            }
            #pragma unroll
            for (int nf = 0; nf < 4; ++nf) {
                mma16816(acc0[nf], a0, b0f + nf * 2);
                mma16816(acc1[nf], &wi1f[kf * 4], b0f + nf * 2);
            }
        }

        // exchange acc0
        #pragma unroll
        for (int nf = 0; nf < 4; ++nf)
            #pragma unroll
            for (int q = 0; q < 4; ++q) {
                int m = (lane >> 2) + 8 * (q >> 1);
                int n = nf * 8 + 2 * (lane & 3) + (q & 1);
                red0[((kh * 4 + mf) * 16 + m) * 33 + n] = acc0[nf][q];
            }
        __syncthreads();    // S1: phase-A reads of H0 done; red0 ready

        // epi0: h0[t] publish
        if (t < T_) {
            char* w0g = (char*)(w0 + (size_t)b0 * H_);
            #pragma unroll
            for (int cell = 0; cell < 2; ++cell) {
                int jl = ej + cell * 8;
                float pre[4];
                #pragma unroll
                for (int g = 0; g < 4; ++g)
                    pre[g] = red0[(g * 16 + jl) * 33 + eb]
                           + red0[((4 + g) * 16 + jl) * 33 + eb];
                float ii = sigm_f(pre[0]), ff = sigm_f(pre[1]);
                float gg = tanh_f(pre[2]), oo = sigm_f(pre[3]);
                float& cc = cell ? c0b : c0a;
                cc = ff * cc + ii * gg;
                *(__half*)(w0g + swz_off(j0 + jl)) = __float2half(oo * tanh_f(cc));
            }
            __syncthreads();    // S2: all h0 STGs issued
            if (tid == 0) {
                __threadfence();
                asm volatile("st.relaxed.gpu.u32 [%0], %1;"
                             :: "l"(myflag + 0), "r"((unsigned)(t + 1)) : "memory");
            }
            // warp0: close the h0 chain — poll group flag0, issue next h0 TMA
            // (overlaps with phase B on warps 1-7)
            if (wid == 0 && t + 1 <= T_) {
                unsigned int* fp = &g_flags[(grp * 32 + lane) * 32];
                unsigned int v;
                do {
                    asm volatile("ld.acquire.gpu.u32 %0, [%1];"
                                 : "=r"(v) : "l"(fp) : "memory");
                } while (__any_sync(0xffffffffu, v < (unsigned)(t + 1)));
                if (lane == 0) {
                    MBARRIER_EXPECT_TX(mbA, 32768u);
                    TMA_BULK_G2S(sb + LSM_H0, (const char*)(w0 + (size_t)b0 * H_),
                                 32768u, mbA);
                }
            }
        }

        // ================= PHASE B: h1 tile =================
        mbar_wait(mbB, (uint32_t)(t & 1));

        #pragma unroll
        for (int kf = 0; kf < 16; ++kf) {
            int kfa = kh * 16 + kf;
            int c = kfa >> 2, ks = kfa & 3;
            uint32_t a1[4], b1f[8];
            uint32_t arow = SWZ128((uint32_t)(a_row * 128 + ks * 32 + a_kb));
            ldsm_x4(a1, sb + LSM_W1 + c * 8192 + arow);
            #pragma unroll
            for (int nfp = 0; nfp < 2; ++nfp) {
                uint32_t bo = SWZ128((uint32_t)((nfp * 16 + b_row) * 128 + ks * 32 + b_kb));
                ldsm_x4(b1f + nfp * 4, sb + LSM_H1 + c * 4096 + bo);
            }
            #pragma unroll
            for (int nf = 0; nf < 4; ++nf)
                mma16816(acc1[nf], a1, b1f + nf * 2);
        }

        // exchange acc1
        #pragma unroll
        for (int nf = 0; nf < 4; ++nf)
            #pragma unroll
            for (int q = 0; q < 4; ++q) {
                int m = (lane >> 2) + 8 * (q >> 1);
                int n = nf * 8 + 2 * (lane & 3) + (q & 1);
                red1[((kh * 4 + mf) * 16 + m) * 33 + n] = acc1[nf][q];
            }
        __syncthreads();    // S3: phase-B reads of H1 done; red1 ready

        // epi1: h1[t-1] publish (+ final fp32 at t == T)
        if (t >= 1) {
            char* w1g = (char*)(w1 + (size_t)b0 * H_);
            #pragma unroll
            for (int cell = 0; cell < 2; ++cell) {
                int jl = ej + cell * 8;
                float pre[4];
                #pragma unroll
                for (int g = 0; g < 4; ++g)
                    pre[g] = red1[(g * 16 + jl) * 33 + eb]
                           + red1[((4 + g) * 16 + jl) * 33 + eb];
                float ii = sigm_f(pre[0]), ff = sigm_f(pre[1]);
                float gg = tanh_f(pre[2]), oo = sigm_f(pre[3]);
                float& cc = cell ? c1b : c1a;
                cc = ff * cc + ii * gg;
                float hv = oo * tanh_f(cc);
                if (t < T_)
                    *(__half*)(w1g + swz_off(j0 + jl)) = __float2half(hv);
                if (t == T_)
                    hfin[(size_t)(b0 + eb) * H_ + j0 + jl] = hv;
            }
        }
        if (t < T_) {
            __syncthreads();    // S4: all h1 STGs issued
            if (tid == 0) {
                __threadfence();
                asm volatile("st.relaxed.gpu.u32 [%0], %1;"
                             :: "l"(myflag + 8), "r"((unsigned)(t + 1)) : "memory");
            }
            // warp1: close the h1 chain — poll group flag1, issue next h1 TMA
            if (wid == 1) {
                unsigned int* fp = &g_flags[(grp * 32 + lane) * 32] + 8;
                unsigned int v;
                do {
                    asm volatile("ld.acquire.gpu.u32 %0, [%1];"
                                 : "=r"(v) : "l"(fp) : "memory");
                } while (__any_sync(0xffffffffu, v < (unsigned)(t + 1)));
                if (lane == 0) {
                    MBARRIER_EXPECT_TX(mbB, 32768u);
                    TMA_BULK_G2S(sb + LSM_H1, (const char*)(w1 + (size_t)b0 * H_),
                                 32768u, mbB);
                }
            }
        }
    }
}

// ---------------- fc head -----------------------------------------------------------
__global__ void fc_kernel(const float* __restrict__ h,
                          const float* __restrict__ W,
                          const float* __restrict__ bias,
                          float* __restrict__ out)
{
    int tid = threadIdx.x;
    int b = tid >> 1, o = tid & 1;
    float s = bias[o];
    const float* hp = h + (size_t)b * H_;
    const float* wp = W + (size_t)o * H_;
    for (int k = 0; k < H_; ++k) s = fmaf(hp[k], wp[k], s);
    out[b * OUT_ + o] = s;
}

// ---------------- launch -------------------------------------------------------------
extern "C" void kernel_launch(void* const* d_in, const int* in_sizes, int n_in,
                              void* d_out, int out_size)
{
    const float* x    = (const float*)d_in[0];
    const float* Wih0 = (const float*)d_in[1];
    const float* Whh0 = (const float*)d_in[2];
    const float* bih0 = (const float*)d_in[3];
    const float* bhh0 = (const float*)d_in[4];
    const float* Wih1 = (const float*)d_in[5];
    const float* Whh1 = (const float*)d_in[6];
    const float* bih1 = (const float*)d_in[7];
    const float* bhh1 = (const float*)d_in[8];
    const float* fcW  = (const float*)d_in[9];
    const float* fcb  = (const float*)d_in[10];
    float* out = (float*)d_out;

    float *xg, *hA;
    __half *xth, *xtl, *w0h, *w0l, *wr0, *wr1, *wi1;
    cudaGetSymbolAddress((void**)&xg,  g_xg);
    cudaGetSymbolAddress((void**)&hA,  g_hA);
    cudaGetSymbolAddress((void**)&xth, g_xth);
    cudaGetSymbolAddress((void**)&xtl, g_xtl);
    cudaGetSymbolAddress((void**)&w0h, g_w0h);
    cudaGetSymbolAddress((void**)&w0l, g_w0l);
    cudaGetSymbolAddress((void**)&wr0, g_wr0);
    cudaGetSymbolAddress((void**)&wr1, g_wr1);
    cudaGetSymbolAddress((void**)&wi1, g_wi1);

    cudaFuncSetAttribute(lstm_fused_kernel,
                         cudaFuncAttributeMaxDynamicSharedMemorySize, LSM_TOTAL);
    cudaFuncSetAttribute(gemm_mma_kernel,
                         cudaFuncAttributeMaxDynamicSharedMemorySize, GSM_TOTAL);

    // 1) transpose x -> fp16 hi/lo xt[t][b][d]
    transpose_kernel<<<dim3(T_ / 32, DIN_ / 32, B_), dim3(32, 8)>>>(x);

    // 2) weight prep
    wsplit_kernel<<<(G4H_ * DIN_ + 255) / 256, 256>>>(Wih0, w0h, w0l, G4H_ * DIN_);
    wconv3_kernel<<<dim3((G4H_ * H_ + 255) / 256, 3), 256>>>(
        Whh0, wr0, Whh1, wr1, Wih1, wi1, G4H_ * H_);

    // 3) xg0 = xt @ Wih0^T + bias (fp16 3-product, precision anchor)
    gemm_mma_kernel<<<dim3(G4H_ / 128, T_), 256, GSM_TOTAL>>>(
        xth, xtl, w0h, w0l, bih0, bhh0, xg, DIN_);

    // 4) fused dual-layer recurrence (split-phase, dual-chain pipeline)
    lstm_fused_kernel<<<128, 256, LSM_TOTAL>>>(xg, wr0, wr1, wi1, bih1, bhh1, hA);

    // 5) fc head
    fc_kernel<<<1, 256>>>(hA, fcW, fcb, out);
}

// round 13
// speedup vs baseline: 1.5364x; 1.5364x over previous
#include <cuda_runtime.h>
#include <cuda_fp16.h>
#include <math.h>
#include <stdint.h>
#include <stddef.h>

#define B_   128
#define DIN_ 128
#define T_   1024
#define H_   512
#define G4H_ 2048
#define OUT_ 2

// ---------------- scratch (static device allocations; no cudaMalloc) ----------------
__device__ __half g_xth [(size_t)T_ * B_ * DIN_];  // x transposed, fp16 hi
__device__ __half g_xtl [(size_t)T_ * B_ * DIN_];  // fp16 lo residual
__device__ __half g_w0h [(size_t)G4H_ * DIN_];     // Wih0 hi/lo (GEMM1)
__device__ __half g_w0l [(size_t)G4H_ * DIN_];
__device__ __half g_wr0 [(size_t)G4H_ * H_];       // Whh0 fp16
__device__ __half g_wr1 [(size_t)G4H_ * H_];       // Whh1 fp16
__device__ __half g_wi1 [(size_t)G4H_ * H_];       // Wih1 fp16
// h ping-pong buffers: group-blocked, PRE-SWIZZLED (SW128 smem image), aligned for TMA
__device__ __align__(128) __half g_h0a [B_ * H_];
__device__ __align__(128) __half g_h0b [B_ * H_];
__device__ __align__(128) __half g_h1a [B_ * H_];
__device__ __align__(128) __half g_h1b [B_ * H_];
__device__ float g_xg [(size_t)T_ * G4H_ * B_];    // layer-0 gate preacts [t][n][b]
__device__ float g_hA [B_ * H_];                   // final h1 fp32 for fc
__device__ unsigned int g_bar[4 * 32];             // setup barrier
__device__ unsigned int g_flags[4 * 32 * 32];      // per-CTA step flags, 128B stride

// ---------------- small helpers -----------------------------------------------------
__device__ __forceinline__ void hsplit(float v, __half& h, __half& l) {
    h = __float2half(v);
    l = __float2half(v - __half2float(h));
}
__device__ __forceinline__ uint32_t smem_u32(const void* p) {
    uint32_t a;
    asm("{ .reg .u64 t; cvta.to.shared.u64 t, %1; cvt.u32.u64 %0, t; }" : "=r"(a) : "l"(p));
    return a;
}
#define SWZ128(o) ((o) ^ (((o) >> 3) & 0x70))

__device__ __forceinline__ void ldsm_x4(uint32_t* r, uint32_t addr) {
    asm volatile("ldmatrix.sync.aligned.m8n8.x4.shared.b16 {%0,%1,%2,%3}, [%4];"
        : "=r"(r[0]), "=r"(r[1]), "=r"(r[2]), "=r"(r[3]) : "r"(addr));
}
__device__ __forceinline__ void mma16816(float* d, const uint32_t* a, const uint32_t* b) {
    asm volatile("mma.sync.aligned.m16n8k16.row.col.f32.f16.f16.f32 "
        "{%0,%1,%2,%3}, {%4,%5,%6,%7}, {%8,%9}, {%0,%1,%2,%3};"
        : "+f"(d[0]), "+f"(d[1]), "+f"(d[2]), "+f"(d[3])
        : "r"(a[0]), "r"(a[1]), "r"(a[2]), "r"(a[3]), "r"(b[0]), "r"(b[1]));
}
#define CPASYNC16(dst, src) \
    asm volatile("cp.async.cg.shared.global [%0], [%1], 16;" :: "r"(dst), "l"(src))
#define CPCOMMIT() asm volatile("cp.async.commit_group;" ::: "memory")
#define CPWAIT0()  asm volatile("cp.async.wait_group 0;" ::: "memory")
#define CPWAIT1()  asm volatile("cp.async.wait_group 1;" ::: "memory")

#define MBARRIER_INIT(addr, cnt) \
    asm volatile("mbarrier.init.shared.b64 [%0], %1;" :: "r"(addr), "r"(cnt) : "memory")
#define MBARRIER_EXPECT_TX(addr, tx) \
    asm volatile("mbarrier.arrive.expect_tx.shared.b64 _, [%0], %1;" \
                 :: "r"(addr), "r"(tx) : "memory")
#define TMA_BULK_G2S(dst, src, bytes, mbar) \
    asm volatile("cp.async.bulk.shared::cluster.global.mbarrier::complete_tx::bytes " \
                 "[%0], [%1], %2, [%3];" \
                 :: "r"(dst), "l"(src), "r"(bytes), "r"(mbar) : "memory")
__device__ __forceinline__ void mbar_wait(uint32_t addr, uint32_t parity) {
    uint32_t done = 0;
    while (!done) {
        asm volatile(
            "{\n\t.reg .pred p;\n\t"
            "mbarrier.try_wait.parity.shared.b64 p, [%1], %2, 0x989680;\n\t"
            "selp.b32 %0, 1, 0, p;\n\t}"
            : "=r"(done) : "r"(addr), "r"(parity) : "memory");
    }
}

// ---------------- setup-time barrier (atomic; used once per launch) -------------------
__device__ __forceinline__ void group_barrier(unsigned int* bar) {
    __syncthreads();
    if (threadIdx.x == 0) {
        unsigned int gen;
        asm volatile("ld.acquire.gpu.u32 %0, [%1];" : "=r"(gen) : "l"(bar + 1) : "memory");
        unsigned int arrived;
        asm volatile("atom.add.release.gpu.u32 %0, [%1], 1;"
                     : "=r"(arrived) : "l"(bar) : "memory");
        if (arrived == 31u) {
            asm volatile("st.relaxed.gpu.u32 [%0], 0;" :: "l"(bar) : "memory");
            asm volatile("red.add.release.gpu.u32 [%0], 1;" :: "l"(bar + 1) : "memory");
        } else {
            unsigned int g2;
            do {
                asm volatile("ld.acquire.gpu.u32 %0, [%1];"
                             : "=r"(g2) : "l"(bar + 1) : "memory");
            } while (g2 == gen);
        }
    }
    __syncthreads();
}

// ---------------- transpose x: (B, D, T) -> xt[t][b][d] as fp16 hi/lo ----------------
__global__ void transpose_kernel(const float* __restrict__ x) {
    __shared__ float tile[32][33];
    const int b  = blockIdx.z;
    const int t0 = blockIdx.x * 32;
    const int d0 = blockIdx.y * 32;
    const int tx = threadIdx.x, ty = threadIdx.y;
    #pragma unroll
    for (int i = 0; i < 4; ++i) {
        int d = d0 + ty + i * 8;
        tile[ty + i * 8][tx] = x[((size_t)b * DIN_ + d) * T_ + t0 + tx];
    }
    __syncthreads();
    #pragma unroll
    for (int i = 0; i < 4; ++i) {
        int t = t0 + ty + i * 8;
        float v = tile[tx][ty + i * 8];
        __half h, l;
        hsplit(v, h, l);
        size_t idx = ((size_t)t * B_ + b) * DIN_ + d0 + tx;
        g_xth[idx] = h;
        g_xtl[idx] = l;
    }
}

// ---------------- weight prep -------------------------------------------------------
__global__ void wsplit_kernel(const float* __restrict__ w,
                              __half* __restrict__ wh,
                              __half* __restrict__ wl, int n) {
    int i = blockIdx.x * blockDim.x + threadIdx.x;
    if (i < n) {
        __half h, l;
        hsplit(w[i], h, l);
        wh[i] = h;
        wl[i] = l;
    }
}
__global__ void wconv3_kernel(const float* __restrict__ a, __half* __restrict__ oa,
                              const float* __restrict__ b, __half* __restrict__ ob,
                              const float* __restrict__ c, __half* __restrict__ oc,
                              int n) {
    int i = blockIdx.x * blockDim.x + threadIdx.x;
    if (i >= n) return;
    if (blockIdx.y == 0)      oa[i] = __float2half(a[i]);
    else if (blockIdx.y == 1) ob[i] = __float2half(b[i]);
    else                      oc[i] = __float2half(c[i]);
}

// ---------------- mma.sync split-fp16 GEMM (2-product: Ah*Bh + Ah*Bl) ----------------
#define TILE_BYTES  16384
#define STAGE_BYTES (4 * TILE_BYTES)
#define GSM_TOTAL   (2 * STAGE_BYTES)

__global__ void __launch_bounds__(256, 1)
gemm_mma_kernel(const __half* __restrict__ Ah, const __half* __restrict__ Al,
                const __half* __restrict__ Bh, const __half* __restrict__ Bl,
                const float* __restrict__ bias1, const float* __restrict__ bias2,
                float* __restrict__ C, int K)
{
    extern __shared__ char smem[];
    const uint32_t sb = smem_u32(smem);
    const int tid  = threadIdx.x;
    const int lane = tid & 31;
    const int warp = tid >> 5;
    const int tile_t = blockIdx.y;
    const int n0blk  = blockIdx.x * 128;
    const int m_off = (warp & 3) * 32;
    const int n_off = (warp >> 2) * 64;

    const __half* gsrc[4] = {
        Ah + (size_t)tile_t * 128 * K, Al + (size_t)tile_t * 128 * K,
        Bh + (size_t)n0blk * K,        Bl + (size_t)n0blk * K };

    auto issue_stage = [&](int buf, int kc) {
        #pragma unroll
        for (int i = 0; i < 16; ++i) {
            int id  = tid + i * 256;
            int tl  = id >> 10;
            int rem = id & 1023;
            int row = rem >> 3;
            int ch  = rem & 7;
            const __half* src = gsrc[tl] + (size_t)row * K + kc * 64 + ch * 8;
            uint32_t dst = sb + buf * STAGE_BYTES + tl * TILE_BYTES
                         + SWZ128((uint32_t)(row * 128 + ch * 16));
            CPASYNC16(dst, src);
        }
        CPCOMMIT();
    };

    float acc[2][8][4];
    #pragma unroll
    for (int mf = 0; mf < 2; ++mf)
        #pragma unroll
        for (int nf = 0; nf < 8; ++nf)
            #pragma unroll
            for (int r = 0; r < 4; ++r) acc[mf][nf][r] = 0.f;

    const int nkc = K >> 6;
    issue_stage(0, 0);
    issue_stage(1, 1);

    const int a_row_base = (lane & 7) + ((lane >> 3) & 1) * 8;
    const int a_kh       = (lane >> 4) * 16;
    const int b_row_base = (lane & 7) + ((lane >> 4) & 1) * 8;
    const int b_kh       = ((lane >> 3) & 1) * 16;

    for (int kc = 0; kc < nkc; ++kc) {
        if (kc + 1 < nkc) { CPWAIT1(); } else { CPWAIT0(); }
        __syncthreads();

        const uint32_t st = sb + (kc & 1) * STAGE_BYTES;
        #pragma unroll
        for (int ks = 0; ks < 4; ++ks) {
            uint32_t ah[2][4], bh[16], bl[16];
            #pragma unroll
            for (int mf = 0; mf < 2; ++mf) {
                uint32_t off = SWZ128((uint32_t)((m_off + mf * 16 + a_row_base) * 128
                                                 + ks * 32 + a_kh));
                ldsm_x4(ah[mf], st + 0 * TILE_BYTES + off);
            }
            #pragma unroll
            for (int bf = 0; bf < 4; ++bf) {
                uint32_t off = SWZ128((uint32_t)((n_off + bf * 16 + b_row_base) * 128
                                                 + ks * 32 + b_kh));
                ldsm_x4(bh + bf * 4, st + 2 * TILE_BYTES + off);
                ldsm_x4(bl + bf * 4, st + 3 * TILE_BYTES + off);
            }
            #pragma unroll
            for (int mf = 0; mf < 2; ++mf)
                #pragma unroll
                for (int nf = 0; nf < 8; ++nf) {
                    mma16816(acc[mf][nf], ah[mf], bh + nf * 2);
                    mma16816(acc[mf][nf], ah[mf], bl + nf * 2);
                }
        }
        __syncthreads();
        if (kc + 2 < nkc) issue_stage(kc & 1, kc + 2);
    }

    #pragma unroll
    for (int nf = 0; nf < 8; ++nf) {
        int n = n0blk + n_off + nf * 8 + 2 * (lane & 3);
        float bv0 = __ldg(&bias1[n])     + __ldg(&bias2[n]);
        float bv1 = __ldg(&bias1[n + 1]) + __ldg(&bias2[n + 1]);
        #pragma unroll
        for (int mf = 0; mf < 2; ++mf) {
            int b = m_off + mf * 16 + (lane >> 2);
            float* c0 = &C[((size_t)tile_t * G4H_ + n) * B_ + b];
            c0[0]       = acc[mf][nf][0] + bv0;
            c0[B_]      = acc[mf][nf][1] + bv1;
            c0[8]       = acc[mf][nf][2] + bv0;
            c0[B_ + 8]  = acc[mf][nf][3] + bv1;
        }
    }
}

// ---------------- fused dual-layer persistent LSTM recurrence (R11 + half mbars) -----
// 128 CTAs = 4 b-groups (32 b) x 32 j-tiles (16 j). 256 threads.
// h staged via TMA bulk (pre-swizzled global layout). Split into lo/hi k-halves
// with separate mbarriers so kh=0 warps start MMA as soon as the lo halves land.
#define LSM_W0   0                      // Whh0: 8 chunks x 8192 = 64 KB
#define LSM_W1   65536                  // Whh1: 64 KB
#define LSM_H0   131072                 // h0 tile 32 KB (init: Wih1 temp spans H0+H1)
#define LSM_H1   163840                 // h1 tile 32 KB
#define LSM_RED0 196608                 // 2 kh x 4 g x 16 m x 33 n x 4B = 16896
#define LSM_RED1 213504
#define LSM_MBLO 230400                 // mbarrier: lo halves (h0-lo + h1-lo)
#define LSM_MBHI 230416                 // mbarrier: hi halves
#define LSM_TOTAL 230528

__device__ __forceinline__ float sigm_f(float v) {
    return __fdividef(1.f, 1.f + __expf(-v));
}
__device__ __forceinline__ float tanh_f(float v) {
    return 1.f - __fdividef(2.f, __expf(2.f * v) + 1.f);
}

__global__ void __launch_bounds__(256, 1)
lstm_fused_kernel(const float* __restrict__ xg,      // [t][n][b] (layer-0 preacts)
                  const __half* __restrict__ whh0,
                  const __half* __restrict__ whh1,
                  const __half* __restrict__ wih1,
                  const float* __restrict__ bih1,
                  const float* __restrict__ bhh1,
                  float* __restrict__ hfin)          // final fp32 h1
{
    extern __shared__ char sm[];
    const uint32_t sb = smem_u32(sm);
    float* red0 = (float*)(sm + LSM_RED0);
    float* red1 = (float*)(sm + LSM_RED1);
    const uint32_t mbLo = sb + LSM_MBLO;
    const uint32_t mbHi = sb + LSM_MBHI;

    const int tid  = threadIdx.x;
    const int lane = tid & 31;
    const int wid  = tid >> 5;
    const int grp  = blockIdx.x & 3;
    const int jt   = blockIdx.x >> 2;
    const int b0   = grp * 32;
    const int j0   = jt * 16;
    unsigned int* bar    = g_bar + grp * 32;
    unsigned int* myflag = &g_flags[(grp * 32 + jt) * 32];

    const int mf = wid & 3;              // gate
    const int kh = wid >> 2;             // k-half
    const int a_row = mf * 16 + (lane & 7) + ((lane >> 3) & 1) * 8;
    const int a_kb  = (lane >> 4) * 16;
    const int b_row = (lane & 7) + ((lane >> 4) & 1) * 8;
    const int b_kb  = ((lane >> 3) & 1) * 16;

    // ---- stage Whh0 -> LSM_W0, Whh1 -> LSM_W1, Wih1 -> temp (LSM_H0+H1, 64 KB) ----
    #pragma unroll
    for (int i = 0; i < 16; ++i) {
        int id = tid + i * 256;           // 0..4095 16B-chunks
        int m  = id >> 6, ch = id & 63;
        int g = m >> 4, jl = m & 15;
        size_t roff = ((size_t)(g * H_ + j0 + jl)) * H_ + ch * 8;
        int c = ch >> 3, cc = ch & 7;
        uint32_t soff = c * 8192 + SWZ128((uint32_t)(m * 128 + cc * 16));
        *(uint4*)(sm + LSM_W0 + soff) = *(const uint4*)(whh0 + roff);
        *(uint4*)(sm + LSM_W1 + soff) = *(const uint4*)(whh1 + roff);
        *(uint4*)(sm + LSM_H0 + soff) = *(const uint4*)(wih1 + roff);
    }

    // ---- zero edge h buffers; reset flag; init mbarriers ----
    if (tid < 64) {
        int bl = tid >> 1, p = tid & 1;
        size_t o = (size_t)(b0 + bl) * H_ + j0 + p * 8;
        *(uint4*)&g_h0b[o] = make_uint4(0, 0, 0, 0);
        *(uint4*)&g_h1b[o] = make_uint4(0, 0, 0, 0);
    }
    if (tid == 0) {
        *myflag = 0;
        MBARRIER_INIT(mbLo, 1u);
        MBARRIER_INIT(mbHi, 1u);
    }
    __syncthreads();

    // ---- Wih1 A-fragments -> registers (persist whole kernel) ----
    uint32_t wi1f[64];
    #pragma unroll
    for (int kf = 0; kf < 16; ++kf) {
        int kfa = kh * 16 + kf;
        int c = kfa >> 2, ks = kfa & 3;
        ldsm_x4(&wi1f[kf * 4],
                sb + LSM_H0 + c * 8192 + SWZ128((uint32_t)(a_row * 128 + ks * 32 + a_kb)));
    }

    const int m_lo = lane >> 2;
    float bias_lo = __ldg(&bih1[mf * H_ + j0 + m_lo])     + __ldg(&bhh1[mf * H_ + j0 + m_lo]);
    float bias_hi = __ldg(&bih1[mf * H_ + j0 + m_lo + 8]) + __ldg(&bhh1[mf * H_ + j0 + m_lo + 8]);

    group_barrier(bar);   // setup complete (zeros + flag resets visible group-wide)

    const int eb = tid & 31;
    const int ej = tid >> 5;
    float c0a = 0.f, c0b = 0.f;   // layer-0 cell states
    float c1a = 0.f, c1b = 0.f;   // layer-1 cell states

    // pre-swizzled publish: value for (local batch eb, global k) -> group block offset
    auto swz_off = [&](int k) -> uint32_t {
        int c = k >> 6;
        int cc = (k >> 3) & 7;
        int lo = (k & 7) * 2;
        return (uint32_t)(c * 4096) + SWZ128((uint32_t)(eb * 128 + cc * 16)) + (uint32_t)lo;
    };

    for (int t = 0; t <= T_; ++t) {
        const __half* r0 = (t & 1) ? g_h0a : g_h0b;
        __half*       w0 = (t & 1) ? g_h0b : g_h0a;
        const __half* r1 = (t & 1) ? g_h1b : g_h1a;
        __half*       w1 = (t & 1) ? g_h1a : g_h1b;

        // ---- stage h0[t-1] / h1[t-2] via TMA bulk, split lo/hi halves ----
        if (tid == 0) {
            const char* s0 = (const char*)(r0 + (size_t)b0 * H_);
            const char* s1 = (const char*)(r1 + (size_t)b0 * H_);
            MBARRIER_EXPECT_TX(mbLo, 32768u);
            TMA_BULK_G2S(sb + LSM_H0,         s0,         16384u, mbLo);
            TMA_BULK_G2S(sb + LSM_H1,         s1,         16384u, mbLo);
            MBARRIER_EXPECT_TX(mbHi, 32768u);
            TMA_BULK_G2S(sb + LSM_H0 + 16384, s0 + 16384, 16384u, mbHi);
            TMA_BULK_G2S(sb + LSM_H1 + 16384, s1 + 16384, 16384u, mbHi);
        }

        // ---- acc init: layer-0 from xg0[t] (kh=0), layer-1 from bias (kh=0) ----
        float acc0[4][4], acc1[4][4];
        if (kh == 0) {
            if (t < T_) {
                #pragma unroll
                for (int nf = 0; nf < 4; ++nf)
                    #pragma unroll
                    for (int q = 0; q < 4; ++q) {
                        int jl = (lane >> 2) + 8 * (q >> 1);
                        int bn = nf * 8 + 2 * (lane & 3) + (q & 1);
                        acc0[nf][q] = __ldg(&xg[((size_t)t * G4H_ + mf * H_ + j0 + jl) * B_
                                                + b0 + bn]);
                    }
            } else {
                #pragma unroll
                for (int nf = 0; nf < 4; ++nf)
                    #pragma unroll
                    for (int q = 0; q < 4; ++q) acc0[nf][q] = 0.f;
            }
            #pragma unroll
            for (int nf = 0; nf < 4; ++nf)
                #pragma unroll
                for (int q = 0; q < 4; ++q)
                    acc1[nf][q] = (q & 2) ? bias_hi : bias_lo;
        } else {
            #pragma unroll
            for (int nf = 0; nf < 4; ++nf)
                #pragma unroll
                for (int q = 0; q < 4; ++q) { acc0[nf][q] = 0.f; acc1[nf][q] = 0.f; }
        }

        // ---- wait: each warp waits only its own k-half ----
        mbar_wait(kh == 0 ? mbLo : mbHi, (uint32_t)(t & 1));

        // ---- MMA: acc0 += Whh0@h0 ; acc1 += Wih1@h0 + Whh1@h1 ----
        #pragma unroll
        for (int kf = 0; kf < 16; ++kf) {
            int kfa = kh * 16 + kf;
            int c = kfa >> 2, ks = kfa & 3;
            uint32_t a0[4], a1[4], b0f[8], b1f[8];
            uint32_t arow = SWZ128((uint32_t)(a_row * 128 + ks * 32 + a_kb));
            ldsm_x4(a0, sb + LSM_W0 + c * 8192 + arow);
            ldsm_x4(a1, sb + LSM_W1 + c * 8192 + arow);
            #pragma unroll
            for (int nfp = 0; nfp < 2; ++nfp) {
                uint32_t bo = SWZ128((uint32_t)((nfp * 16 + b_row) * 128 + ks * 32 + b_kb));
                ldsm_x4(b0f + nfp * 4, sb + LSM_H0 + c * 4096 + bo);
                ldsm_x4(b1f + nfp * 4, sb + LSM_H1 + c * 4096 + bo);
            }
            #pragma unroll
            for (int nf = 0; nf < 4; ++nf) {
                mma16816(acc0[nf], a0, b0f + nf * 2);
                mma16816(acc1[nf], &wi1f[kf * 4], b0f + nf * 2);
                mma16816(acc1[nf], a1, b1f + nf * 2);
            }
        }

        // ---- exchange partials: both layers, ONE sync ----
        #pragma unroll
        for (int nf = 0; nf < 4; ++nf)
            #pragma unroll
            for (int q = 0; q < 4; ++q) {
                int m = (lane >> 2) + 8 * (q >> 1);
                int n = nf * 8 + 2 * (lane & 3) + (q & 1);
                int idx = ((kh * 4 + mf) * 16 + m) * 33 + n;
                red0[idx] = acc0[nf][q];
                red1[idx] = acc1[nf][q];
            }
        __syncthreads();

        // ---- epilogues: publish to PRE-SWIZZLED global h buffers ----
        char* w0g = (char*)(w0 + (size_t)b0 * H_);
        char* w1g = (char*)(w1 + (size_t)b0 * H_);
        if (t < T_) {
            #pragma unroll
            for (int cell = 0; cell < 2; ++cell) {
                int jl = ej + cell * 8;
                float pre[4];
                #pragma unroll
                for (int g = 0; g < 4; ++g)
                    pre[g] = red0[(g * 16 + jl) * 33 + eb]
                           + red0[((4 + g) * 16 + jl) * 33 + eb];
                float ii = sigm_f(pre[0]), ff = sigm_f(pre[1]);
                float gg = tanh_f(pre[2]), oo = sigm_f(pre[3]);
                float& cc = cell ? c0b : c0a;
                cc = ff * cc + ii * gg;
                *(__half*)(w0g + swz_off(j0 + jl)) = __float2half(oo * tanh_f(cc));
            }
        }
        if (t >= 1) {
            #pragma unroll
            for (int cell = 0; cell < 2; ++cell) {
                int jl = ej + cell * 8;
                float pre[4];
                #pragma unroll
                for (int g = 0; g < 4; ++g)
                    pre[g] = red1[(g * 16 + jl) * 33 + eb]
                           + red1[((4 + g) * 16 + jl) * 33 + eb];
                float ii = sigm_f(pre[0]), ff = sigm_f(pre[1]);
                float gg = tanh_f(pre[2]), oo = sigm_f(pre[3]);
                float& cc = cell ? c1b : c1a;
                cc = ff * cc + ii * gg;
                float hv = oo * tanh_f(cc);
                if (t < T_)
                    *(__half*)(w1g + swz_off(j0 + jl)) = __float2half(hv);
                if (t == T_)
                    hfin[(size_t)(b0 + eb) * H_ + j0 + jl] = hv;
            }
        }

        // ---- distributed flag barrier ----
        if (t < T_) {
            const unsigned int gen = (unsigned int)(t + 1);
            __syncthreads();                       // publishes done; smem reusable
            if (tid == 0) {
                __threadfence();                   // h stores visible gpu-wide
                asm volatile("st.relaxed.gpu.u32 [%0], %1;"
                             :: "l"(myflag), "r"(gen) : "memory");
            }
            if (wid == 0) {                        // 32 lanes poll 32 producers
                unsigned int* fp = &g_flags[(grp * 32 + lane) * 32];
                unsigned int v;
                do {
                    asm volatile("ld.acquire.gpu.u32 %0, [%1];"
                                 : "=r"(v) : "l"(fp) : "memory");
                } while (__any_sync(0xffffffffu, v < gen));
            }
            __syncthreads();
        }
    }
}

// ---------------- fc head -----------------------------------------------------------
__global__ void fc_kernel(const float* __restrict__ h,
                          const float* __restrict__ W,
                          const float* __restrict__ bias,
                          float* __restrict__ out)
{
    int tid = threadIdx.x;
    int b = tid >> 1, o = tid & 1;
    float s = bias[o];
    const float* hp = h + (size_t)b * H_;
    const float* wp = W + (size_t)o * H_;
    for (int k = 0; k < H_; ++k) s = fmaf(hp[k], wp[k], s);
    out[b * OUT_ + o] = s;
}

// ---------------- launch -------------------------------------------------------------
extern "C" void kernel_launch(void* const* d_in, const int* in_sizes, int n_in,
                              void* d_out, int out_size)
{
    const float* x    = (const float*)d_in[0];
    const float* Wih0 = (const float*)d_in[1];
    const float* Whh0 = (const float*)d_in[2];
    const float* bih0 = (const float*)d_in[3];
    const float* bhh0 = (const float*)d_in[4];
    const float* Wih1 = (const float*)d_in[5];
    const float* Whh1 = (const float*)d_in[6];
    const float* bih1 = (const float*)d_in[7];
    const float* bhh1 = (const float*)d_in[8];
    const float* fcW  = (const float*)d_in[9];
    const float* fcb  = (const float*)d_in[10];
    float* out = (float*)d_out;

    float *xg, *hA;
    __half *xth, *xtl, *w0h, *w0l, *wr0, *wr1, *wi1;
    cudaGetSymbolAddress((void**)&xg,  g_xg);
    cudaGetSymbolAddress((void**)&hA,  g_hA);
    cudaGetSymbolAddress((void**)&xth, g_xth);
    cudaGetSymbolAddress((void**)&xtl, g_xtl);
    cudaGetSymbolAddress((void**)&w0h, g_w0h);
    cudaGetSymbolAddress((void**)&w0l, g_w0l);
    cudaGetSymbolAddress((void**)&wr0, g_wr0);
    cudaGetSymbolAddress((void**)&wr1, g_wr1);
    cudaGetSymbolAddress((void**)&wi1, g_wi1);

    cudaFuncSetAttribute(lstm_fused_kernel,
                         cudaFuncAttributeMaxDynamicSharedMemorySize, LSM_TOTAL);
    cudaFuncSetAttribute(gemm_mma_kernel,
                         cudaFuncAttributeMaxDynamicSharedMemorySize, GSM_TOTAL);

    // 1) transpose x -> fp16 hi/lo xt[t][b][d]
    transpose_kernel<<<dim3(T_ / 32, DIN_ / 32, B_), dim3(32, 8)>>>(x);

    // 2) weight prep
    wsplit_kernel<<<(G4H_ * DIN_ + 255) / 256, 256>>>(Wih0, w0h, w0l, G4H_ * DIN_);
    wconv3_kernel<<<dim3((G4H_ * H_ + 255) / 256, 3), 256>>>(
        Whh0, wr0, Whh1, wr1, Wih1, wi1, G4H_ * H_);

    // 3) xg0 = xt @ Wih0^T + bias (fp16 2-product)
    gemm_mma_kernel<<<dim3(G4H_ / 128, T_), 256, GSM_TOTAL>>>(
        xth, xtl, w0h, w0l, bih0, bhh0, xg, DIN_);

    // 4) fused dual-layer recurrence (R11 structure + half-tile mbarriers)
    lstm_fused_kernel<<<128, 256, LSM_TOTAL>>>(xg, wr0, wr1, wi1, bih1, bhh1, hA);

    // 5) fc head
    fc_kernel<<<1, 256>>>(hA, fcW, fcb, out);
}

// round 14
// speedup vs baseline: 1.6450x; 1.0707x over previous
#include <cuda_runtime.h>
#include <cuda_fp16.h>
#include <math.h>
#include <stdint.h>
#include <stddef.h>

#define B_   128
#define DIN_ 128
#define T_   1024
#define H_   512
#define G4H_ 2048
#define OUT_ 2

// ---------------- scratch (static device allocations; no cudaMalloc) ----------------
__device__ __half g_xth [(size_t)T_ * B_ * DIN_];  // x transposed, fp16 hi
__device__ __half g_xtl [(size_t)T_ * B_ * DIN_];  // fp16 lo residual
__device__ __half g_wi0 [(size_t)G4H_ * DIN_];     // Wih0 fp16
__device__ __half g_wr0 [(size_t)G4H_ * H_];       // Whh0 fp16
__device__ __half g_wr1 [(size_t)G4H_ * H_];       // Whh1 fp16
__device__ __half g_wi1 [(size_t)G4H_ * H_];       // Wih1 fp16
// h ping-pong buffers: group-blocked, PRE-SWIZZLED (SW128 smem image), aligned for TMA
__device__ __align__(128) __half g_h0a [B_ * H_];
__device__ __align__(128) __half g_h0b [B_ * H_];
__device__ __align__(128) __half g_h1a [B_ * H_];
__device__ __align__(128) __half g_h1b [B_ * H_];
__device__ float g_hA [B_ * H_];                   // final h1 fp32 for fc
__device__ unsigned int g_bar[4 * 32];             // setup barrier
__device__ unsigned int g_flags[4 * 32 * 32];      // per-CTA step flags, 128B stride

// ---------------- small helpers -----------------------------------------------------
__device__ __forceinline__ void hsplit(float v, __half& h, __half& l) {
    h = __float2half(v);
    l = __float2half(v - __half2float(h));
}
__device__ __forceinline__ uint32_t smem_u32(const void* p) {
    uint32_t a;
    asm("{ .reg .u64 t; cvta.to.shared.u64 t, %1; cvt.u32.u64 %0, t; }" : "=r"(a) : "l"(p));
    return a;
}
#define SWZ128(o) ((o) ^ (((o) >> 3) & 0x70))

__device__ __forceinline__ void ldsm_x4(uint32_t* r, uint32_t addr) {
    asm volatile("ldmatrix.sync.aligned.m8n8.x4.shared.b16 {%0,%1,%2,%3}, [%4];"
        : "=r"(r[0]), "=r"(r[1]), "=r"(r[2]), "=r"(r[3]) : "r"(addr));
}
__device__ __forceinline__ void mma16816(float* d, const uint32_t* a, const uint32_t* b) {
    asm volatile("mma.sync.aligned.m16n8k16.row.col.f32.f16.f16.f32 "
        "{%0,%1,%2,%3}, {%4,%5,%6,%7}, {%8,%9}, {%0,%1,%2,%3};"
        : "+f"(d[0]), "+f"(d[1]), "+f"(d[2]), "+f"(d[3])
        : "r"(a[0]), "r"(a[1]), "r"(a[2]), "r"(a[3]), "r"(b[0]), "r"(b[1]));
}
#define CPASYNC16(dst, src) \
    asm volatile("cp.async.cg.shared.global [%0], [%1], 16;" :: "r"(dst), "l"(src))
#define CPCOMMIT() asm volatile("cp.async.commit_group;" ::: "memory")
#define CPWAIT0()  asm volatile("cp.async.wait_group 0;" ::: "memory")

#define MBARRIER_INIT(addr, cnt) \
    asm volatile("mbarrier.init.shared.b64 [%0], %1;" :: "r"(addr), "r"(cnt) : "memory")
#define MBARRIER_EXPECT_TX(addr, tx) \
    asm volatile("mbarrier.arrive.expect_tx.shared.b64 _, [%0], %1;" \
                 :: "r"(addr), "r"(tx) : "memory")
#define TMA_BULK_G2S(dst, src, bytes, mbar) \
    asm volatile("cp.async.bulk.shared::cluster.global.mbarrier::complete_tx::bytes " \
                 "[%0], [%1], %2, [%3];" \
                 :: "r"(dst), "l"(src), "r"(bytes), "r"(mbar) : "memory")
__device__ __forceinline__ void mbar_wait(uint32_t addr, uint32_t parity) {
    uint32_t done = 0;
    while (!done) {
        asm volatile(
            "{\n\t.reg .pred p;\n\t"
            "mbarrier.try_wait.parity.shared.b64 p, [%1], %2, 0x989680;\n\t"
            "selp.b32 %0, 1, 0, p;\n\t}"
            : "=r"(done) : "r"(addr), "r"(parity) : "memory");
    }
}

// ---------------- setup-time barrier (atomic; used once per launch) -------------------
__device__ __forceinline__ void group_barrier(unsigned int* bar) {
    __syncthreads();
    if (threadIdx.x == 0) {
        unsigned int gen;
        asm volatile("ld.acquire.gpu.u32 %0, [%1];" : "=r"(gen) : "l"(bar + 1) : "memory");
        unsigned int arrived;
        asm volatile("atom.add.release.gpu.u32 %0, [%1], 1;"
                     : "=r"(arrived) : "l"(bar) : "memory");
        if (arrived == 31u) {
            asm volatile("st.relaxed.gpu.u32 [%0], 0;" :: "l"(bar) : "memory");
            asm volatile("red.add.release.gpu.u32 [%0], 1;" :: "l"(bar + 1) : "memory");
        } else {
            unsigned int g2;
            do {
                asm volatile("ld.acquire.gpu.u32 %0, [%1];"
                             : "=r"(g2) : "l"(bar + 1) : "memory");
            } while (g2 == gen);
        }
    }
    __syncthreads();
}

// ---------------- transpose x: (B, D, T) -> xt[t][b][d] as fp16 hi/lo ----------------
__global__ void transpose_kernel(const float* __restrict__ x) {
    __shared__ float tile[32][33];
    const int b  = blockIdx.z;
    const int t0 = blockIdx.x * 32;
    const int d0 = blockIdx.y * 32;
    const int tx = threadIdx.x, ty = threadIdx.y;
    #pragma unroll
    for (int i = 0; i < 4; ++i) {
        int d = d0 + ty + i * 8;
        tile[ty + i * 8][tx] = x[((size_t)b * DIN_ + d) * T_ + t0 + tx];
    }
    __syncthreads();
    #pragma unroll
    for (int i = 0; i < 4; ++i) {
        int t = t0 + ty + i * 8;
        float v = tile[tx][ty + i * 8];
        __half h, l;
        hsplit(v, h, l);
        size_t idx = ((size_t)t * B_ + b) * DIN_ + d0 + tx;
        g_xth[idx] = h;
        g_xtl[idx] = l;
    }
}

// ---------------- weight prep -------------------------------------------------------
__global__ void wconv3_kernel(const float* __restrict__ a, __half* __restrict__ oa,
                              const float* __restrict__ b, __half* __restrict__ ob,
                              const float* __restrict__ c, __half* __restrict__ oc,
                              int n) {
    int i = blockIdx.x * blockDim.x + threadIdx.x;
    if (i >= n) return;
    if (blockIdx.y == 0)      oa[i] = __float2half(a[i]);
    else if (blockIdx.y == 1) ob[i] = __float2half(b[i]);
    else                      oc[i] = __float2half(c[i]);
}
__global__ void wconv1_kernel(const float* __restrict__ a, __half* __restrict__ oa,
                              int n) {
    int i = blockIdx.x * blockDim.x + threadIdx.x;
    if (i < n) oa[i] = __float2half(a[i]);
}

// ---------------- fully-fused dual-layer persistent LSTM ------------------------------
// 128 CTAs = 4 b-groups (32 b) x 32 j-tiles (16 j). 256 threads.
// Per step: acc0 = bias0 + Wih0@x[t] (regs A, x staged in red0 area) + Whh0@h0;
//           acc1 = bias1 + Wih1@h0 + Whh1@h1. No separate GEMM1, no xg buffer.
#define LSM_W0   0                      // Whh0: 8 chunks x 8192 = 64 KB
#define LSM_W1   65536                  // Whh1: 64 KB
#define LSM_H0   131072                 // h0 tile 32 KB (init: Wih1 temp spans H0+H1)
#define LSM_H1   163840                 // h1 tile 32 KB
#define LSM_RED0 196608                 // 16896 B; doubles as x[t] staging (16384 B)
#define LSM_RED1 213504                 // 16896 B
#define LSM_MBLO 230400                 // mbarrier: lo halves (h0-lo + h1-lo)
#define LSM_MBHI 230416                 // mbarrier: hi halves
#define LSM_TOTAL 230528

__device__ __forceinline__ float sigm_f(float v) {
    return __fdividef(1.f, 1.f + __expf(-v));
}
__device__ __forceinline__ float tanh_f(float v) {
    return 1.f - __fdividef(2.f, __expf(2.f * v) + 1.f);
}

__global__ void __launch_bounds__(256, 1)
lstm_fused_kernel(const __half* __restrict__ whh0,
                  const __half* __restrict__ whh1,
                  const __half* __restrict__ wih1,
                  const __half* __restrict__ wih0,
                  const float* __restrict__ bih0,
                  const float* __restrict__ bhh0,
                  const float* __restrict__ bih1,
                  const float* __restrict__ bhh1,
                  float* __restrict__ hfin)          // final fp32 h1
{
    extern __shared__ char sm[];
    const uint32_t sb = smem_u32(sm);
    float* red0 = (float*)(sm + LSM_RED0);
    float* red1 = (float*)(sm + LSM_RED1);
    const uint32_t mbLo = sb + LSM_MBLO;
    const uint32_t mbHi = sb + LSM_MBHI;

    const int tid  = threadIdx.x;
    const int lane = tid & 31;
    const int wid  = tid >> 5;
    const int grp  = blockIdx.x & 3;
    const int jt   = blockIdx.x >> 2;
    const int b0   = grp * 32;
    const int j0   = jt * 16;
    unsigned int* bar    = g_bar + grp * 32;
    unsigned int* myflag = &g_flags[(grp * 32 + jt) * 32];

    const int mf = wid & 3;              // gate
    const int kh = wid >> 2;             // k-half
    const int a_row = mf * 16 + (lane & 7) + ((lane >> 3) & 1) * 8;
    const int a_kb  = (lane >> 4) * 16;
    const int b_row = (lane & 7) + ((lane >> 4) & 1) * 8;
    const int b_kb  = ((lane >> 3) & 1) * 16;

    // ---- stage Whh0 -> LSM_W0, Whh1 -> LSM_W1, Wih1 -> temp (LSM_H0+H1, 64 KB) ----
    #pragma unroll
    for (int i = 0; i < 16; ++i) {
        int id = tid + i * 256;           // 0..4095 16B-chunks
        int m  = id >> 6, ch = id & 63;
        int g = m >> 4, jl = m & 15;
        size_t roff = ((size_t)(g * H_ + j0 + jl)) * H_ + ch * 8;
        int c = ch >> 3, cc = ch & 7;
        uint32_t soff = c * 8192 + SWZ128((uint32_t)(m * 128 + cc * 16));
        *(uint4*)(sm + LSM_W0 + soff) = *(const uint4*)(whh0 + roff);
        *(uint4*)(sm + LSM_W1 + soff) = *(const uint4*)(whh1 + roff);
        *(uint4*)(sm + LSM_H0 + soff) = *(const uint4*)(wih1 + roff);
    }

    // ---- zero edge h buffers; reset flag; init mbarriers ----
    if (tid < 64) {
        int bl = tid >> 1, p = tid & 1;
        size_t o = (size_t)(b0 + bl) * H_ + j0 + p * 8;
        *(uint4*)&g_h0b[o] = make_uint4(0, 0, 0, 0);
        *(uint4*)&g_h1b[o] = make_uint4(0, 0, 0, 0);
    }
    if (tid == 0) {
        *myflag = 0;
        MBARRIER_INIT(mbLo, 1u);
        MBARRIER_INIT(mbHi, 1u);
    }
    __syncthreads();

    // ---- Wih1 A-fragments -> registers ----
    uint32_t wi1f[64];
    #pragma unroll
    for (int kf = 0; kf < 16; ++kf) {
        int kfa = kh * 16 + kf;
        int c = kfa >> 2, ks = kfa & 3;
        ldsm_x4(&wi1f[kf * 4],
                sb + LSM_H0 + c * 8192 + SWZ128((uint32_t)(a_row * 128 + ks * 32 + a_kb)));
    }
    __syncthreads();   // wi1f loaded everywhere before H0 overwrite

    // ---- stage Wih0 (64 rows x 128 d fp16, 16 KB) into H0; frags -> registers ----
    #pragma unroll
    for (int i = 0; i < 4; ++i) {
        int id = tid + i * 256;           // 0..1023 16B-chunks
        int m  = id >> 4, ch = id & 15;
        int g = m >> 4, jl = m & 15;
        size_t roff = ((size_t)(g * H_ + j0 + jl)) * DIN_ + ch * 8;
        int c = ch >> 3, cc = ch & 7;
        uint32_t soff = c * 8192 + SWZ128((uint32_t)(m * 128 + cc * 16));
        *(uint4*)(sm + LSM_H0 + soff) = *(const uint4*)(wih0 + roff);
    }
    __syncthreads();
    uint32_t wi0f[16];
    #pragma unroll
    for (int kf = 0; kf < 4; ++kf) {
        int kfa = kh * 4 + kf;
        int c = kfa >> 2, ks = kfa & 3;
        ldsm_x4(&wi0f[kf * 4],
                sb + LSM_H0 + c * 8192 + SWZ128((uint32_t)(a_row * 128 + ks * 32 + a_kb)));
    }

    const int m_lo = lane >> 2;
    float bias0_lo = __ldg(&bih0[mf * H_ + j0 + m_lo])     + __ldg(&bhh0[mf * H_ + j0 + m_lo]);
    float bias0_hi = __ldg(&bih0[mf * H_ + j0 + m_lo + 8]) + __ldg(&bhh0[mf * H_ + j0 + m_lo + 8]);
    float bias1_lo = __ldg(&bih1[mf * H_ + j0 + m_lo])     + __ldg(&bhh1[mf * H_ + j0 + m_lo]);
    float bias1_hi = __ldg(&bih1[mf * H_ + j0 + m_lo + 8]) + __ldg(&bhh1[mf * H_ + j0 + m_lo + 8]);

    group_barrier(bar);   // setup complete

    const int eb = tid & 31;
    const int ej = tid >> 5;
    float c0a = 0.f, c0b = 0.f;   // layer-0 cell states
    float c1a = 0.f, c1b = 0.f;   // layer-1 cell states

    // pre-swizzled publish offset
    auto swz_off = [&](int k) -> uint32_t {
        int c = k >> 6;
        int cc = (k >> 3) & 7;
        int lo = (k & 7) * 2;
        return (uint32_t)(c * 4096) + SWZ128((uint32_t)(eb * 128 + cc * 16)) + (uint32_t)lo;
    };

    for (int t = 0; t <= T_; ++t) {
        const __half* r0 = (t & 1) ? g_h0a : g_h0b;
        __half*       w0 = (t & 1) ? g_h0b : g_h0a;
        const __half* r1 = (t & 1) ? g_h1b : g_h1a;
        __half*       w1 = (t & 1) ? g_h1a : g_h1b;

        // ---- stage x[t] hi/lo into red0 area (16 KB), 4 cp.async per thread ----
        if (t < T_) {
            #pragma unroll
            for (int i = 0; i < 4; ++i) {
                int id  = tid + i * 256;          // 0..1023
                int hl  = id >> 9;
                int rem = id & 511;
                int bl  = rem >> 4, ch = rem & 15;
                const __half* src = (hl ? g_xtl : g_xth)
                    + ((size_t)t * B_ + b0 + bl) * DIN_ + ch * 8;
                int c = ch >> 3, cc = ch & 7;
                uint32_t dst = sb + LSM_RED0 + hl * 8192 + c * 4096
                             + SWZ128((uint32_t)(bl * 128 + cc * 16));
                CPASYNC16(dst, src);
            }
            CPCOMMIT();
        }

        // ---- stage h0[t-1] / h1[t-2] via TMA bulk, split lo/hi halves ----
        if (tid == 0) {
            const char* s0 = (const char*)(r0 + (size_t)b0 * H_);
            const char* s1 = (const char*)(r1 + (size_t)b0 * H_);
            MBARRIER_EXPECT_TX(mbLo, 32768u);
            TMA_BULK_G2S(sb + LSM_H0,         s0,         16384u, mbLo);
            TMA_BULK_G2S(sb + LSM_H1,         s1,         16384u, mbLo);
            MBARRIER_EXPECT_TX(mbHi, 32768u);
            TMA_BULK_G2S(sb + LSM_H0 + 16384, s0 + 16384, 16384u, mbHi);
            TMA_BULK_G2S(sb + LSM_H1 + 16384, s1 + 16384, 16384u, mbHi);
        }

        // ---- acc init from biases (kh=0 only) ----
        float acc0[4][4], acc1[4][4];
        #pragma unroll
        for (int nf = 0; nf < 4; ++nf)
            #pragma unroll
            for (int q = 0; q < 4; ++q) {
                acc0[nf][q] = (kh == 0) ? ((q & 2) ? bias0_hi : bias0_lo) : 0.f;
                acc1[nf][q] = (kh == 0) ? ((q & 2) ? bias1_hi : bias1_lo) : 0.f;
            }

        // ---- x-MMA: acc0 += Wih0@(xh + xl)  (x staged in red0 area) ----
        if (t < T_) {
            CPWAIT0();
            __syncthreads();     // S_x: all x chunks visible
            #pragma unroll
            for (int kf = 0; kf < 4; ++kf) {
                int kfa = kh * 4 + kf;
                int c = kfa >> 2, ks = kfa & 3;
                uint32_t xh[8], xl[8];
                #pragma unroll
                for (int nfp = 0; nfp < 2; ++nfp) {
                    uint32_t bo = SWZ128((uint32_t)((nfp * 16 + b_row) * 128
                                                     + ks * 32 + b_kb));
                    ldsm_x4(xh + nfp * 4, sb + LSM_RED0        + c * 4096 + bo);
                    ldsm_x4(xl + nfp * 4, sb + LSM_RED0 + 8192 + c * 4096 + bo);
                }
                #pragma unroll
                for (int nf = 0; nf < 4; ++nf) {
                    mma16816(acc0[nf], &wi0f[kf * 4], xh + nf * 2);
                    mma16816(acc0[nf], &wi0f[kf * 4], xl + nf * 2);
                }
            }
            __syncthreads();     // S_x2: x reads done before red0 exchange writes
        }

        // ---- wait own h k-half, then main MMA ----
        mbar_wait(kh == 0 ? mbLo : mbHi, (uint32_t)(t & 1));

        #pragma unroll
        for (int kf = 0; kf < 16; ++kf) {
            int kfa = kh * 16 + kf;
            int c = kfa >> 2, ks = kfa & 3;
            uint32_t a0[4], a1[4], b0f[8], b1f[8];
            uint32_t arow = SWZ128((uint32_t)(a_row * 128 + ks * 32 + a_kb));
            ldsm_x4(a0, sb + LSM_W0 + c * 8192 + arow);
            ldsm_x4(a1, sb + LSM_W1 + c * 8192 + arow);
            #pragma unroll
            for (int nfp = 0; nfp < 2; ++nfp) {
                uint32_t bo = SWZ128((uint32_t)((nfp * 16 + b_row) * 128 + ks * 32 + b_kb));
                ldsm_x4(b0f + nfp * 4, sb + LSM_H0 + c * 4096 + bo);
                ldsm_x4(b1f + nfp * 4, sb + LSM_H1 + c * 4096 + bo);
            }
            #pragma unroll
            for (int nf = 0; nf < 4; ++nf) {
                mma16816(acc0[nf], a0, b0f + nf * 2);
                mma16816(acc1[nf], &wi1f[kf * 4], b0f + nf * 2);
                mma16816(acc1[nf], a1, b1f + nf * 2);
            }
        }

        // ---- exchange partials: both layers, ONE sync ----
        #pragma unroll
        for (int nf = 0; nf < 4; ++nf)
            #pragma unroll
            for (int q = 0; q < 4; ++q) {
                int m = (lane >> 2) + 8 * (q >> 1);
                int n = nf * 8 + 2 * (lane & 3) + (q & 1);
                int idx = ((kh * 4 + mf) * 16 + m) * 33 + n;
                red0[idx] = acc0[nf][q];
                red1[idx] = acc1[nf][q];
            }
        __syncthreads();

        // ---- epilogues: publish to PRE-SWIZZLED global h buffers ----
        char* w0g = (char*)(w0 + (size_t)b0 * H_);
        char* w1g = (char*)(w1 + (size_t)b0 * H_);
        if (t < T_) {
            #pragma unroll
            for (int cell = 0; cell < 2; ++cell) {
                int jl = ej + cell * 8;
                float pre[4];
                #pragma unroll
                for (int g = 0; g < 4; ++g)
                    pre[g] = red0[(g * 16 + jl) * 33 + eb]
                           + red0[((4 + g) * 16 + jl) * 33 + eb];
                float ii = sigm_f(pre[0]), ff = sigm_f(pre[1]);
                float gg = tanh_f(pre[2]), oo = sigm_f(pre[3]);
                float& cc = cell ? c0b : c0a;
                cc = ff * cc + ii * gg;
                *(__half*)(w0g + swz_off(j0 + jl)) = __float2half(oo * tanh_f(cc));
            }
        }
        if (t >= 1) {
            #pragma unroll
            for (int cell = 0; cell < 2; ++cell) {
                int jl = ej + cell * 8;
                float pre[4];
                #pragma unroll
                for (int g = 0; g < 4; ++g)
                    pre[g] = red1[(g * 16 + jl) * 33 + eb]
                           + red1[((4 + g) * 16 + jl) * 33 + eb];
                float ii = sigm_f(pre[0]), ff = sigm_f(pre[1]);
                float gg = tanh_f(pre[2]), oo = sigm_f(pre[3]);
                float& cc = cell ? c1b : c1a;
                cc = ff * cc + ii * gg;
                float hv = oo * tanh_f(cc);
                if (t < T_)
                    *(__half*)(w1g + swz_off(j0 + jl)) = __float2half(hv);
                if (t == T_)
                    hfin[(size_t)(b0 + eb) * H_ + j0 + jl] = hv;
            }
        }

        // ---- distributed flag barrier ----
        if (t < T_) {
            const unsigned int gen = (unsigned int)(t + 1);
            __syncthreads();                       // publishes done; smem reusable
            if (tid == 0) {
                __threadfence();                   // h stores visible gpu-wide
                asm volatile("st.relaxed.gpu.u32 [%0], %1;"
                             :: "l"(myflag), "r"(gen) : "memory");
            }
            if (wid == 0) {                        // 32 lanes poll 32 producers
                unsigned int* fp = &g_flags[(grp * 32 + lane) * 32];
                unsigned int v;
                do {
                    asm volatile("ld.acquire.gpu.u32 %0, [%1];"
                                 : "=r"(v) : "l"(fp) : "memory");
                } while (__any_sync(0xffffffffu, v < gen));
            }
            __syncthreads();
        }
    }
}

// ---------------- fc head -----------------------------------------------------------
__global__ void fc_kernel(const float* __restrict__ h,
                          const float* __restrict__ W,
                          const float* __restrict__ bias,
                          float* __restrict__ out)
{
    int tid = threadIdx.x;
    int b = tid >> 1, o = tid & 1;
    float s = bias[o];
    const float* hp = h + (size_t)b * H_;
    const float* wp = W + (size_t)o * H_;
    for (int k = 0; k < H_; ++k) s = fmaf(hp[k], wp[k], s);
    out[b * OUT_ + o] = s;
}

// ---------------- launch -------------------------------------------------------------
extern "C" void kernel_launch(void* const* d_in, const int* in_sizes, int n_in,
                              void* d_out, int out_size)
{
    const float* x    = (const float*)d_in[0];
    const float* Wih0 = (const float*)d_in[1];
    const float* Whh0 = (const float*)d_in[2];
    const float* bih0 = (const float*)d_in[3];
    const float* bhh0 = (const float*)d_in[4];
    const float* Wih1 = (const float*)d_in[5];
    const float* Whh1 = (const float*)d_in[6];
    const float* bih1 = (const float*)d_in[7];
    const float* bhh1 = (const float*)d_in[8];
    const float* fcW  = (const float*)d_in[9];
    const float* fcb  = (const float*)d_in[10];
    float* out = (float*)d_out;

    float* hA;
    __half *wi0, *wr0, *wr1, *wi1;
    cudaGetSymbolAddress((void**)&hA,  g_hA);
    cudaGetSymbolAddress((void**)&wi0, g_wi0);
    cudaGetSymbolAddress((void**)&wr0, g_wr0);
    cudaGetSymbolAddress((void**)&wr1, g_wr1);
    cudaGetSymbolAddress((void**)&wi1, g_wi1);

    cudaFuncSetAttribute(lstm_fused_kernel,
                         cudaFuncAttributeMaxDynamicSharedMemorySize, LSM_TOTAL);

    // 1) transpose x -> fp16 hi/lo xt[t][b][d]
    transpose_kernel<<<dim3(T_ / 32, DIN_ / 32, B_), dim3(32, 8)>>>(x);

    // 2) weight prep (all single fp16)
    wconv3_kernel<<<dim3((G4H_ * H_ + 255) / 256, 3), 256>>>(
        Whh0, wr0, Whh1, wr1, Wih1, wi1, G4H_ * H_);
    wconv1_kernel<<<(G4H_ * DIN_ + 255) / 256, 256>>>(Wih0, wi0, G4H_ * DIN_);

    // 3) fully-fused dual-layer recurrence (x-GEMM folded in; no xg buffer)
    lstm_fused_kernel<<<128, 256, LSM_TOTAL>>>(wr0, wr1, wi1, wi0,
                                               bih0, bhh0, bih1, bhh1, hA);

    // 4) fc head
    fc_kernel<<<1, 256>>>(hA, fcW, fcb, out);
}

// round 15
// speedup vs baseline: 1.6820x; 1.0225x over previous
#include <cuda_runtime.h>
#include <cuda_fp16.h>
#include <math.h>
#include <stdint.h>
#include <stddef.h>

#define B_   128
#define DIN_ 128
#define T_   1024
#define H_   512
#define G4H_ 2048
#define OUT_ 2

// ---------------- scratch (static device allocations; no cudaMalloc) ----------------
__device__ __half g_xth [(size_t)T_ * B_ * DIN_];  // x transposed, fp16 hi
__device__ __half g_xtl [(size_t)T_ * B_ * DIN_];  // fp16 lo residual
__device__ __half g_wi0 [(size_t)G4H_ * DIN_];     // Wih0 fp16
__device__ __half g_wr0 [(size_t)G4H_ * H_];       // Whh0 fp16
__device__ __half g_wr1 [(size_t)G4H_ * H_];       // Whh1 fp16
__device__ __half g_wi1 [(size_t)G4H_ * H_];       // Wih1 fp16
// h ping-pong buffers: group-blocked, PRE-SWIZZLED (SW128 smem image), aligned for TMA
__device__ __align__(128) __half g_h0a [B_ * H_];
__device__ __align__(128) __half g_h0b [B_ * H_];
__device__ __align__(128) __half g_h1a [B_ * H_];
__device__ __align__(128) __half g_h1b [B_ * H_];
__device__ float g_hA [B_ * H_];                   // final h1 fp32 for fc
__device__ unsigned int g_bar[4 * 32];             // setup barrier
__device__ unsigned int g_flags[4 * 32 * 32];      // per-CTA step flags, 128B stride

// ---------------- small helpers -----------------------------------------------------
__device__ __forceinline__ void hsplit(float v, __half& h, __half& l) {
    h = __float2half(v);
    l = __float2half(v - __half2float(h));
}
__device__ __forceinline__ uint32_t smem_u32(const void* p) {
    uint32_t a;
    asm("{ .reg .u64 t; cvta.to.shared.u64 t, %1; cvt.u32.u64 %0, t; }" : "=r"(a) : "l"(p));
    return a;
}
#define SWZ128(o) ((o) ^ (((o) >> 3) & 0x70))

__device__ __forceinline__ void ldsm_x4(uint32_t* r, uint32_t addr) {
    asm volatile("ldmatrix.sync.aligned.m8n8.x4.shared.b16 {%0,%1,%2,%3}, [%4];"
        : "=r"(r[0]), "=r"(r[1]), "=r"(r[2]), "=r"(r[3]) : "r"(addr));
}
__device__ __forceinline__ void mma16816(float* d, const uint32_t* a, const uint32_t* b) {
    asm volatile("mma.sync.aligned.m16n8k16.row.col.f32.f16.f16.f32 "
        "{%0,%1,%2,%3}, {%4,%5,%6,%7}, {%8,%9}, {%0,%1,%2,%3};"
        : "+f"(d[0]), "+f"(d[1]), "+f"(d[2]), "+f"(d[3])
        : "r"(a[0]), "r"(a[1]), "r"(a[2]), "r"(a[3]), "r"(b[0]), "r"(b[1]));
}
#define CPASYNC16(dst, src) \
    asm volatile("cp.async.cg.shared.global [%0], [%1], 16;" :: "r"(dst), "l"(src))
#define CPCOMMIT() asm volatile("cp.async.commit_group;" ::: "memory")
#define CPWAIT0()  asm volatile("cp.async.wait_group 0;" ::: "memory")

#define MBARRIER_INIT(addr, cnt) \
    asm volatile("mbarrier.init.shared.b64 [%0], %1;" :: "r"(addr), "r"(cnt) : "memory")
#define MBARRIER_EXPECT_TX(addr, tx) \
    asm volatile("mbarrier.arrive.expect_tx.shared.b64 _, [%0], %1;" \
                 :: "r"(addr), "r"(tx) : "memory")
#define TMA_BULK_G2S(dst, src, bytes, mbar) \
    asm volatile("cp.async.bulk.shared::cluster.global.mbarrier::complete_tx::bytes " \
                 "[%0], [%1], %2, [%3];" \
                 :: "r"(dst), "l"(src), "r"(bytes), "r"(mbar) : "memory")
__device__ __forceinline__ void mbar_wait(uint32_t addr, uint32_t parity) {
    uint32_t done = 0;
    while (!done) {
        asm volatile(
            "{\n\t.reg .pred p;\n\t"
            "mbarrier.try_wait.parity.shared.b64 p, [%1], %2, 0x989680;\n\t"
            "selp.b32 %0, 1, 0, p;\n\t}"
            : "=r"(done) : "r"(addr), "r"(parity) : "memory");
    }
}

// ---------------- setup-time barrier (atomic; used once per launch) -------------------
__device__ __forceinline__ void group_barrier(unsigned int* bar) {
    __syncthreads();
    if (threadIdx.x == 0) {
        unsigned int gen;
        asm volatile("ld.acquire.gpu.u32 %0, [%1];" : "=r"(gen) : "l"(bar + 1) : "memory");
        unsigned int arrived;
        asm volatile("atom.add.release.gpu.u32 %0, [%1], 1;"
                     : "=r"(arrived) : "l"(bar) : "memory");
        if (arrived == 31u) {
            asm volatile("st.relaxed.gpu.u32 [%0], 0;" :: "l"(bar) : "memory");
            asm volatile("red.add.release.gpu.u32 [%0], 1;" :: "l"(bar + 1) : "memory");
        } else {
            unsigned int g2;
            do {
                asm volatile("ld.acquire.gpu.u32 %0, [%1];"
                             : "=r"(g2) : "l"(bar + 1) : "memory");
            } while (g2 == gen);
        }
    }
    __syncthreads();
}

// ---------------- transpose x: (B, D, T) -> xt[t][b][d] as fp16 hi/lo ----------------
__global__ void transpose_kernel(const float* __restrict__ x) {
    __shared__ float tile[32][33];
    const int b  = blockIdx.z;
    const int t0 = blockIdx.x * 32;
    const int d0 = blockIdx.y * 32;
    const int tx = threadIdx.x, ty = threadIdx.y;
    #pragma unroll
    for (int i = 0; i < 4; ++i) {
        int d = d0 + ty + i * 8;
        tile[ty + i * 8][tx] = x[((size_t)b * DIN_ + d) * T_ + t0 + tx];
    }
    __syncthreads();
    #pragma unroll
    for (int i = 0; i < 4; ++i) {
        int t = t0 + ty + i * 8;
        float v = tile[tx][ty + i * 8];
        __half h, l;
        hsplit(v, h, l);
        size_t idx = ((size_t)t * B_ + b) * DIN_ + d0 + tx;
        g_xth[idx] = h;
        g_xtl[idx] = l;
    }
}

// ---------------- weight prep -------------------------------------------------------
__global__ void wconv3_kernel(const float* __restrict__ a, __half* __restrict__ oa,
                              const float* __restrict__ b, __half* __restrict__ ob,
                              const float* __restrict__ c, __half* __restrict__ oc,
                              int n) {
    int i = blockIdx.x * blockDim.x + threadIdx.x;
    if (i >= n) return;
    if (blockIdx.y == 0)      oa[i] = __float2half(a[i]);
    else if (blockIdx.y == 1) ob[i] = __float2half(b[i]);
    else                      oc[i] = __float2half(c[i]);
}
__global__ void wconv1_kernel(const float* __restrict__ a, __half* __restrict__ oa,
                              int n) {
    int i = blockIdx.x * blockDim.x + threadIdx.x;
    if (i < n) oa[i] = __float2half(a[i]);
}

// ---------------- fully-fused dual-layer persistent LSTM ------------------------------
// 128 CTAs = 4 b-groups (32 b) x 32 j-tiles (16 j). 256 threads.
// x[t+1] prefetched into the barrier-wait window; TMA issued on poll-detect;
// activations via tanh.approx (MUFU.TANH).
#define LSM_W0   0                      // Whh0: 8 chunks x 8192 = 64 KB
#define LSM_W1   65536                  // Whh1: 64 KB
#define LSM_H0   131072                 // h0 tile 32 KB (init: Wih1 temp spans H0+H1)
#define LSM_H1   163840                 // h1 tile 32 KB
#define LSM_RED0 196608                 // 16896 B; doubles as x staging (16384 B)
#define LSM_RED1 213504                 // 16896 B
#define LSM_MBLO 230400                 // mbarrier: lo halves (h0-lo + h1-lo)
#define LSM_MBHI 230416                 // mbarrier: hi halves
#define LSM_TOTAL 230528

__device__ __forceinline__ float tanh_f(float v) {
    float r;
    asm("tanh.approx.f32 %0, %1;" : "=f"(r) : "f"(v));
    return r;
}
__device__ __forceinline__ float sigm_f(float v) {
    return fmaf(tanh_f(v * 0.5f), 0.5f, 0.5f);
}

__global__ void __launch_bounds__(256, 1)
lstm_fused_kernel(const __half* __restrict__ whh0,
                  const __half* __restrict__ whh1,
                  const __half* __restrict__ wih1,
                  const __half* __restrict__ wih0,
                  const float* __restrict__ bih0,
                  const float* __restrict__ bhh0,
                  const float* __restrict__ bih1,
                  const float* __restrict__ bhh1,
                  float* __restrict__ hfin)          // final fp32 h1
{
    extern __shared__ char sm[];
    const uint32_t sb = smem_u32(sm);
    float* red0 = (float*)(sm + LSM_RED0);
    float* red1 = (float*)(sm + LSM_RED1);
    const uint32_t mbLo = sb + LSM_MBLO;
    const uint32_t mbHi = sb + LSM_MBHI;

    const int tid  = threadIdx.x;
    const int lane = tid & 31;
    const int wid  = tid >> 5;
    const int grp  = blockIdx.x & 3;
    const int jt   = blockIdx.x >> 2;
    const int b0   = grp * 32;
    const int j0   = jt * 16;
    unsigned int* bar    = g_bar + grp * 32;
    unsigned int* myflag = &g_flags[(grp * 32 + jt) * 32];

    const int mf = wid & 3;              // gate
    const int kh = wid >> 2;             // k-half
    const int a_row = mf * 16 + (lane & 7) + ((lane >> 3) & 1) * 8;
    const int a_kb  = (lane >> 4) * 16;
    const int b_row = (lane & 7) + ((lane >> 4) & 1) * 8;
    const int b_kb  = ((lane >> 3) & 1) * 16;

    // ---- stage Whh0 -> LSM_W0, Whh1 -> LSM_W1, Wih1 -> temp (LSM_H0+H1, 64 KB) ----
    #pragma unroll
    for (int i = 0; i < 16; ++i) {
        int id = tid + i * 256;           // 0..4095 16B-chunks
        int m  = id >> 6, ch = id & 63;
        int g = m >> 4, jl = m & 15;
        size_t roff = ((size_t)(g * H_ + j0 + jl)) * H_ + ch * 8;
        int c = ch >> 3, cc = ch & 7;
        uint32_t soff = c * 8192 + SWZ128((uint32_t)(m * 128 + cc * 16));
        *(uint4*)(sm + LSM_W0 + soff) = *(const uint4*)(whh0 + roff);
        *(uint4*)(sm + LSM_W1 + soff) = *(const uint4*)(whh1 + roff);
        *(uint4*)(sm + LSM_H0 + soff) = *(const uint4*)(wih1 + roff);
    }

    // ---- zero edge h buffers; reset flag; init mbarriers ----
    if (tid < 64) {
        int bl = tid >> 1, p = tid & 1;
        size_t o = (size_t)(b0 + bl) * H_ + j0 + p * 8;
        *(uint4*)&g_h0b[o] = make_uint4(0, 0, 0, 0);
        *(uint4*)&g_h1b[o] = make_uint4(0, 0, 0, 0);
    }
    if (tid == 0) {
        *myflag = 0;
        MBARRIER_INIT(mbLo, 1u);
        MBARRIER_INIT(mbHi, 1u);
    }
    __syncthreads();

    // ---- Wih1 A-fragments -> registers ----
    uint32_t wi1f[64];
    #pragma unroll
    for (int kf = 0; kf < 16; ++kf) {
        int kfa = kh * 16 + kf;
        int c = kfa >> 2, ks = kfa & 3;
        ldsm_x4(&wi1f[kf * 4],
                sb + LSM_H0 + c * 8192 + SWZ128((uint32_t)(a_row * 128 + ks * 32 + a_kb)));
    }
    __syncthreads();   // wi1f loaded everywhere before H0 overwrite

    // ---- stage Wih0 (64 rows x 128 d fp16, 16 KB) into H0; frags -> registers ----
    #pragma unroll
    for (int i = 0; i < 4; ++i) {
        int id = tid + i * 256;           // 0..1023 16B-chunks
        int m  = id >> 4, ch = id & 15;
        int g = m >> 4, jl = m & 15;
        size_t roff = ((size_t)(g * H_ + j0 + jl)) * DIN_ + ch * 8;
        int c = ch >> 3, cc = ch & 7;
        uint32_t soff = c * 8192 + SWZ128((uint32_t)(m * 128 + cc * 16));
        *(uint4*)(sm + LSM_H0 + soff) = *(const uint4*)(wih0 + roff);
    }
    __syncthreads();
    uint32_t wi0f[16];
    #pragma unroll
    for (int kf = 0; kf < 4; ++kf) {
        int kfa = kh * 4 + kf;
        int c = kfa >> 2, ks = kfa & 3;
        ldsm_x4(&wi0f[kf * 4],
                sb + LSM_H0 + c * 8192 + SWZ128((uint32_t)(a_row * 128 + ks * 32 + a_kb)));
    }

    const int m_lo = lane >> 2;
    float bias0_lo = __ldg(&bih0[mf * H_ + j0 + m_lo])     + __ldg(&bhh0[mf * H_ + j0 + m_lo]);
    float bias0_hi = __ldg(&bih0[mf * H_ + j0 + m_lo + 8]) + __ldg(&bhh0[mf * H_ + j0 + m_lo + 8]);
    float bias1_lo = __ldg(&bih1[mf * H_ + j0 + m_lo])     + __ldg(&bhh1[mf * H_ + j0 + m_lo]);
    float bias1_hi = __ldg(&bih1[mf * H_ + j0 + m_lo + 8]) + __ldg(&bhh1[mf * H_ + j0 + m_lo + 8]);

    group_barrier(bar);   // setup complete

    // x staging into red0 area (hi 8 KB + lo 8 KB), chunked-SW128
    auto stage_x = [&](int tt) {
        #pragma unroll
        for (int i = 0; i < 4; ++i) {
            int id  = tid + i * 256;          // 0..1023
            int hl  = id >> 9;
            int rem = id & 511;
            int bl  = rem >> 4, ch = rem & 15;
            const __half* src = (hl ? g_xtl : g_xth)
                + ((size_t)tt * B_ + b0 + bl) * DIN_ + ch * 8;
            int c = ch >> 3, cc = ch & 7;
            uint32_t dst = sb + LSM_RED0 + hl * 8192 + c * 4096
                         + SWZ128((uint32_t)(bl * 128 + cc * 16));
            CPASYNC16(dst, src);
        }
        CPCOMMIT();
    };

    // ---- initial: x[0] prefetch + TMA for t=0 ----
    stage_x(0);
    if (tid == 0) {
        const char* s0 = (const char*)(g_h0b + (size_t)b0 * H_);
        const char* s1 = (const char*)(g_h1a + (size_t)b0 * H_);   // t=0 h1 input unused
        MBARRIER_EXPECT_TX(mbLo, 32768u);
        TMA_BULK_G2S(sb + LSM_H0,         s0,         16384u, mbLo);
        TMA_BULK_G2S(sb + LSM_H1,         s1,         16384u, mbLo);
        MBARRIER_EXPECT_TX(mbHi, 32768u);
        TMA_BULK_G2S(sb + LSM_H0 + 16384, s0 + 16384, 16384u, mbHi);
        TMA_BULK_G2S(sb + LSM_H1 + 16384, s1 + 16384, 16384u, mbHi);
    }

    const int eb = tid & 31;
    const int ej = tid >> 5;
    float c0a = 0.f, c0b = 0.f;   // layer-0 cell states
    float c1a = 0.f, c1b = 0.f;   // layer-1 cell states

    auto swz_off = [&](int k) -> uint32_t {
        int c = k >> 6;
        int cc = (k >> 3) & 7;
        int lo = (k & 7) * 2;
        return (uint32_t)(c * 4096) + SWZ128((uint32_t)(eb * 128 + cc * 16)) + (uint32_t)lo;
    };

    for (int t = 0; t <= T_; ++t) {
        __half* w0 = (t & 1) ? g_h0b : g_h0a;   // h0[t] destination
        __half* w1 = (t & 1) ? g_h1a : g_h1b;   // h1[t-1] destination

        // ---- acc init from biases (kh=0 only) ----
        float acc0[4][4], acc1[4][4];
        #pragma unroll
        for (int nf = 0; nf < 4; ++nf)
            #pragma unroll
            for (int q = 0; q < 4; ++q) {
                acc0[nf][q] = (kh == 0) ? ((q & 2) ? bias0_hi : bias0_lo) : 0.f;
                acc1[nf][q] = (kh == 0) ? ((q & 2) ? bias1_hi : bias1_lo) : 0.f;
            }

        // ---- x-MMA: acc0 += Wih0@(xh + xl)  (x prefetched into red0 area) ----
        if (t < T_) {
            CPWAIT0();
            __syncthreads();     // S_x: all x chunks visible
            #pragma unroll
            for (int kf = 0; kf < 4; ++kf) {
                int kfa = kh * 4 + kf;
                int c = kfa >> 2, ks = kfa & 3;
                uint32_t xh[8], xl[8];
                #pragma unroll
                for (int nfp = 0; nfp < 2; ++nfp) {
                    uint32_t bo = SWZ128((uint32_t)((nfp * 16 + b_row) * 128
                                                     + ks * 32 + b_kb));
                    ldsm_x4(xh + nfp * 4, sb + LSM_RED0        + c * 4096 + bo);
                    ldsm_x4(xl + nfp * 4, sb + LSM_RED0 + 8192 + c * 4096 + bo);
                }
                #pragma unroll
                for (int nf = 0; nf < 4; ++nf) {
                    mma16816(acc0[nf], &wi0f[kf * 4], xh + nf * 2);
                    mma16816(acc0[nf], &wi0f[kf * 4], xl + nf * 2);
                }
            }
            __syncthreads();     // S_x2: x reads done before red0 exchange writes
        }

        // ---- wait own h k-half, then main MMA ----
        mbar_wait(kh == 0 ? mbLo : mbHi, (uint32_t)(t & 1));

        #pragma unroll
        for (int kf = 0; kf < 16; ++kf) {
            int kfa = kh * 16 + kf;
            int c = kfa >> 2, ks = kfa & 3;
            uint32_t a0[4], a1[4], b0f[8], b1f[8];
            uint32_t arow = SWZ128((uint32_t)(a_row * 128 + ks * 32 + a_kb));
            ldsm_x4(a0, sb + LSM_W0 + c * 8192 + arow);
            ldsm_x4(a1, sb + LSM_W1 + c * 8192 + arow);
            #pragma unroll
            for (int nfp = 0; nfp < 2; ++nfp) {
                uint32_t bo = SWZ128((uint32_t)((nfp * 16 + b_row) * 128 + ks * 32 + b_kb));
                ldsm_x4(b0f + nfp * 4, sb + LSM_H0 + c * 4096 + bo);
                ldsm_x4(b1f + nfp * 4, sb + LSM_H1 + c * 4096 + bo);
            }
            #pragma unroll
            for (int nf = 0; nf < 4; ++nf) {
                mma16816(acc0[nf], a0, b0f + nf * 2);
                mma16816(acc1[nf], &wi1f[kf * 4], b0f + nf * 2);
                mma16816(acc1[nf], a1, b1f + nf * 2);
            }
        }

        // ---- exchange partials: both layers, ONE sync ----
        #pragma unroll
        for (int nf = 0; nf < 4; ++nf)
            #pragma unroll
            for (int q = 0; q < 4; ++q) {
                int m = (lane >> 2) + 8 * (q >> 1);
                int n = nf * 8 + 2 * (lane & 3) + (q & 1);
                int idx = ((kh * 4 + mf) * 16 + m) * 33 + n;
                red0[idx] = acc0[nf][q];
                red1[idx] = acc1[nf][q];
            }
        __syncthreads();

        // ---- epilogues: publish to PRE-SWIZZLED global h buffers ----
        char* w0g = (char*)(w0 + (size_t)b0 * H_);
        char* w1g = (char*)(w1 + (size_t)b0 * H_);
        if (t < T_) {
            #pragma unroll
            for (int cell = 0; cell < 2; ++cell) {
                int jl = ej + cell * 8;
                float pre[4];
                #pragma unroll
                for (int g = 0; g < 4; ++g)
                    pre[g] = red0[(g * 16 + jl) * 33 + eb]
                           + red0[((4 + g) * 16 + jl) * 33 + eb];
                float ii = sigm_f(pre[0]), ff = sigm_f(pre[1]);
                float gg = tanh_f(pre[2]), oo = sigm_f(pre[3]);
                float& cc = cell ? c0b : c0a;
                cc = ff * cc + ii * gg;
                *(__half*)(w0g + swz_off(j0 + jl)) = __float2half(oo * tanh_f(cc));
            }
        }
        if (t >= 1) {
            #pragma unroll
            for (int cell = 0; cell < 2; ++cell) {
                int jl = ej + cell * 8;
                float pre[4];
                #pragma unroll
                for (int g = 0; g < 4; ++g)
                    pre[g] = red1[(g * 16 + jl) * 33 + eb]
                           + red1[((4 + g) * 16 + jl) * 33 + eb];
                float ii = sigm_f(pre[0]), ff = sigm_f(pre[1]);
                float gg = tanh_f(pre[2]), oo = sigm_f(pre[3]);
                float& cc = cell ? c1b : c1a;
                cc = ff * cc + ii * gg;
                float hv = oo * tanh_f(cc);
                if (t < T_)
                    *(__half*)(w1g + swz_off(j0 + jl)) = __float2half(hv);
                if (t == T_)
                    hfin[(size_t)(b0 + eb) * H_ + j0 + jl] = hv;
            }
        }

        // ---- barrier window: flag store, x[t+1] prefetch, poll, TMA-on-detect ----
        if (t < T_) {
            const unsigned int gen = (unsigned int)(t + 1);
            __syncthreads();                       // publishes done; red0/red1 reusable
            if (tid == 0) {
                __threadfence();                   // h stores visible gpu-wide
                asm volatile("st.relaxed.gpu.u32 [%0], %1;"
                             :: "l"(myflag), "r"(gen) : "memory");
            }
            if (t + 1 < T_) stage_x(t + 1);        // overlaps with the poll below
            if (wid == 0) {                        // 32 lanes poll 32 producers
                unsigned int* fp = &g_flags[(grp * 32 + lane) * 32];
                unsigned int v;
                do {
                    asm volatile("ld.acquire.gpu.u32 %0, [%1];"
                                 : "=r"(v) : "l"(fp) : "memory");
                } while (__any_sync(0xffffffffu, v < gen));
                if (lane == 0) {                   // issue next h TMA on detect
                    const char* s0 = (const char*)(w0 + (size_t)b0 * H_);
                    const char* s1 = (const char*)(w1 + (size_t)b0 * H_);
                    MBARRIER_EXPECT_TX(mbLo, 32768u);
                    TMA_BULK_G2S(sb + LSM_H0,         s0,         16384u, mbLo);
                    TMA_BULK_G2S(sb + LSM_H1,         s1,         16384u, mbLo);
                    MBARRIER_EXPECT_TX(mbHi, 32768u);
                    TMA_BULK_G2S(sb + LSM_H0 + 16384, s0 + 16384, 16384u, mbHi);
                    TMA_BULK_G2S(sb + LSM_H1 + 16384, s1 + 16384, 16384u, mbHi);
                }
            }
            __syncthreads();
        }
    }
}

// ---------------- fc head -----------------------------------------------------------
__global__ void fc_kernel(const float* __restrict__ h,
                          const float* __restrict__ W,
                          const float* __restrict__ bias,
                          float* __restrict__ out)
{
    int tid = threadIdx.x;
    int b = tid >> 1, o = tid & 1;
    float s = bias[o];
    const float* hp = h + (size_t)b * H_;
    const float* wp = W + (size_t)o * H_;
    for (int k = 0; k < H_; ++k) s = fmaf(hp[k], wp[k], s);
    out[b * OUT_ + o] = s;
}

// ---------------- launch -------------------------------------------------------------
extern "C" void kernel_launch(void* const* d_in, const int* in_sizes, int n_in,
                              void* d_out, int out_size)
{
    const float* x    = (const float*)d_in[0];
    const float* Wih0 = (const float*)d_in[1];
    const float* Whh0 = (const float*)d_in[2];
    const float* bih0 = (const float*)d_in[3];
    const float* bhh0 = (const float*)d_in[4];
    const float* Wih1 = (const float*)d_in[5];
    const float* Whh1 = (const float*)d_in[6];
    const float* bih1 = (const float*)d_in[7];
    const float* bhh1 = (const float*)d_in[8];
    const float* fcW  = (const float*)d_in[9];
    const float* fcb  = (const float*)d_in[10];
    float* out = (float*)d_out;

    float* hA;
    __half *wi0, *wr0, *wr1, *wi1;
    cudaGetSymbolAddress((void**)&hA,  g_hA);
    cudaGetSymbolAddress((void**)&wi0, g_wi0);
    cudaGetSymbolAddress((void**)&wr0, g_wr0);
    cudaGetSymbolAddress((void**)&wr1, g_wr1);
    cudaGetSymbolAddress((void**)&wi1, g_wi1);

    cudaFuncSetAttribute(lstm_fused_kernel,
                         cudaFuncAttributeMaxDynamicSharedMemorySize, LSM_TOTAL);

    // 1) transpose x -> fp16 hi/lo xt[t][b][d]
    transpose_kernel<<<dim3(T_ / 32, DIN_ / 32, B_), dim3(32, 8)>>>(x);

    // 2) weight prep (all single fp16)
    wconv3_kernel<<<dim3((G4H_ * H_ + 255) / 256, 3), 256>>>(
        Whh0, wr0, Whh1, wr1, Wih1, wi1, G4H_ * H_);
    wconv1_kernel<<<(G4H_ * DIN_ + 255) / 256, 256>>>(Wih0, wi0, G4H_ * DIN_);

    // 3) fully-fused dual-layer recurrence
    lstm_fused_kernel<<<128, 256, LSM_TOTAL>>>(wr0, wr1, wi1, wi0,
                                               bih0, bhh0, bih1, bhh1, hA);

    // 4) fc head
    fc_kernel<<<1, 256>>>(hA, fcW, fcb, out);
}

// round 16
// speedup vs baseline: 2.0672x; 1.2290x over previous
#include <cuda_runtime.h>
#include <cuda_fp16.h>
#include <math.h>
#include <stdint.h>
#include <stddef.h>

#define B_   128
#define DIN_ 128
#define T_   1024
#define H_   512
#define G4H_ 2048
#define OUT_ 2

// ---------------- scratch (static device allocations; no cudaMalloc) ----------------
__device__ __half g_xth [(size_t)T_ * B_ * DIN_];  // x transposed, fp16 hi
__device__ __half g_xtl [(size_t)T_ * B_ * DIN_];  // fp16 lo residual
__device__ __half g_wi0 [(size_t)G4H_ * DIN_];     // Wih0 fp16
__device__ __half g_wr0 [(size_t)G4H_ * H_];       // Whh0 fp16
__device__ __half g_wr1 [(size_t)G4H_ * H_];       // Whh1 fp16
__device__ __half g_wi1 [(size_t)G4H_ * H_];       // Wih1 fp16
// h ping-pong buffers: group-blocked, PRE-SWIZZLED (SW128 smem image), aligned for TMA
__device__ __align__(128) __half g_h0a [B_ * H_];
__device__ __align__(128) __half g_h0b [B_ * H_];
__device__ __align__(128) __half g_h1a [B_ * H_];
__device__ __align__(128) __half g_h1b [B_ * H_];
__device__ float g_hA [B_ * H_];                   // final h1 fp32 for fc
__device__ unsigned int g_bar[4 * 32];             // setup barrier
__device__ unsigned int g_flags[4 * 32 * 32];      // per-CTA step flags, 128B stride

// ---------------- small helpers -----------------------------------------------------
__device__ __forceinline__ void hsplit(float v, __half& h, __half& l) {
    h = __float2half(v);
    l = __float2half(v - __half2float(h));
}
__device__ __forceinline__ uint32_t smem_u32(const void* p) {
    uint32_t a;
    asm("{ .reg .u64 t; cvta.to.shared.u64 t, %1; cvt.u32.u64 %0, t; }" : "=r"(a) : "l"(p));
    return a;
}
#define SWZ128(o) ((o) ^ (((o) >> 3) & 0x70))

__device__ __forceinline__ void ldsm_x4(uint32_t* r, uint32_t addr) {
    asm volatile("ldmatrix.sync.aligned.m8n8.x4.shared.b16 {%0,%1,%2,%3}, [%4];"
        : "=r"(r[0]), "=r"(r[1]), "=r"(r[2]), "=r"(r[3]) : "r"(addr));
}
__device__ __forceinline__ void mma16816(float* d, const uint32_t* a, const uint32_t* b) {
    asm volatile("mma.sync.aligned.m16n8k16.row.col.f32.f16.f16.f32 "
        "{%0,%1,%2,%3}, {%4,%5,%6,%7}, {%8,%9}, {%0,%1,%2,%3};"
        : "+f"(d[0]), "+f"(d[1]), "+f"(d[2]), "+f"(d[3])
        : "r"(a[0]), "r"(a[1]), "r"(a[2]), "r"(a[3]), "r"(b[0]), "r"(b[1]));
}
#define CPASYNC16(dst, src) \
    asm volatile("cp.async.cg.shared.global [%0], [%1], 16;" :: "r"(dst), "l"(src))
#define CPCOMMIT() asm volatile("cp.async.commit_group;" ::: "memory")
#define CPWAIT0()  asm volatile("cp.async.wait_group 0;" ::: "memory")

#define MBARRIER_INIT(addr, cnt) \
    asm volatile("mbarrier.init.shared.b64 [%0], %1;" :: "r"(addr), "r"(cnt) : "memory")
#define MBARRIER_EXPECT_TX(addr, tx) \
    asm volatile("mbarrier.arrive.expect_tx.shared.b64 _, [%0], %1;" \
                 :: "r"(addr), "r"(tx) : "memory")
#define TMA_BULK_G2S(dst, src, bytes, mbar) \
    asm volatile("cp.async.bulk.shared::cluster.global.mbarrier::complete_tx::bytes " \
                 "[%0], [%1], %2, [%3];" \
                 :: "r"(dst), "l"(src), "r"(bytes), "r"(mbar) : "memory")
__device__ __forceinline__ void mbar_wait(uint32_t addr, uint32_t parity) {
    uint32_t done = 0;
    while (!done) {
        asm volatile(
            "{\n\t.reg .pred p;\n\t"
            "mbarrier.try_wait.parity.shared.b64 p, [%1], %2, 0x989680;\n\t"
            "selp.b32 %0, 1, 0, p;\n\t}"
            : "=r"(done) : "r"(addr), "r"(parity) : "memory");
    }
}

// ---------------- setup-time barrier (atomic; used once per launch) -------------------
__device__ __forceinline__ void group_barrier(unsigned int* bar) {
    __syncthreads();
    if (threadIdx.x == 0) {
        unsigned int gen;
        asm volatile("ld.acquire.gpu.u32 %0, [%1];" : "=r"(gen) : "l"(bar + 1) : "memory");
        unsigned int arrived;
        asm volatile("atom.add.release.gpu.u32 %0, [%1], 1;"
                     : "=r"(arrived) : "l"(bar) : "memory");
        if (arrived == 31u) {
            asm volatile("st.relaxed.gpu.u32 [%0], 0;" :: "l"(bar) : "memory");
            asm volatile("red.add.release.gpu.u32 [%0], 1;" :: "l"(bar + 1) : "memory");
        } else {
            unsigned int g2;
            do {
                asm volatile("ld.acquire.gpu.u32 %0, [%1];"
                             : "=r"(g2) : "l"(bar + 1) : "memory");
            } while (g2 == gen);
        }
    }
    __syncthreads();
}

// ---------------- transpose x: (B, D, T) -> xt[t][b][d] as fp16 hi/lo ----------------
__global__ void transpose_kernel(const float* __restrict__ x) {
    __shared__ float tile[32][33];
    const int b  = blockIdx.z;
    const int t0 = blockIdx.x * 32;
    const int d0 = blockIdx.y * 32;
    const int tx = threadIdx.x, ty = threadIdx.y;
    #pragma unroll
    for (int i = 0; i < 4; ++i) {
        int d = d0 + ty + i * 8;
        tile[ty + i * 8][tx] = x[((size_t)b * DIN_ + d) * T_ + t0 + tx];
    }
    __syncthreads();
    #pragma unroll
    for (int i = 0; i < 4; ++i) {
        int t = t0 + ty + i * 8;
        float v = tile[tx][ty + i * 8];
        __half h, l;
        hsplit(v, h, l);
        size_t idx = ((size_t)t * B_ + b) * DIN_ + d0 + tx;
        g_xth[idx] = h;
        g_xtl[idx] = l;
    }
}

// ---------------- weight prep -------------------------------------------------------
__global__ void wconv3_kernel(const float* __restrict__ a, __half* __restrict__ oa,
                              const float* __restrict__ b, __half* __restrict__ ob,
                              const float* __restrict__ c, __half* __restrict__ oc,
                              int n) {
    int i = blockIdx.x * blockDim.x + threadIdx.x;
    if (i >= n) return;
    if (blockIdx.y == 0)      oa[i] = __float2half(a[i]);
    else if (blockIdx.y == 1) ob[i] = __float2half(b[i]);
    else                      oc[i] = __float2half(c[i]);
}
__global__ void wconv1_kernel(const float* __restrict__ a, __half* __restrict__ oa,
                              int n) {
    int i = blockIdx.x * blockDim.x + threadIdx.x;
    if (i < n) oa[i] = __float2half(a[i]);
}

// ---------------- fully-fused dual-layer persistent LSTM ------------------------------
// 128 CTAs = 4 b-groups (32 b) x 32 j-tiles (16 j). 256 threads.
// Coalesced h publish: epilogue gathers into smem (dead H0 tail), 16B STGs.
#define LSM_W0   0                      // Whh0: 8 chunks x 8192 = 64 KB
#define LSM_W1   65536                  // Whh1: 64 KB
#define LSM_H0   131072                 // h0 tile 32 KB (init: Wih1 temp spans H0+H1)
#define LSM_H1   163840                 // h1 tile 32 KB
#define LSM_RED0 196608                 // 16896 B; doubles as x staging (16384 B)
#define LSM_RED1 213504                 // 16896 B
#define LSM_MBLO 230400                 // mbarrier: lo halves (h0-lo + h1-lo)
#define LSM_MBHI 230416                 // mbarrier: hi halves
#define LSM_TOTAL 230528
// hout staging lives in the dead tail of the H0 tile (safe between last ldsm and next TMA)
#define LSM_HOUT0 (LSM_H0 + 30720)      // 1 KB
#define LSM_HOUT1 (LSM_H0 + 31744)      // 1 KB

__device__ __forceinline__ float tanh_f(float v) {
    float r;
    asm("tanh.approx.f32 %0, %1;" : "=f"(r) : "f"(v));
    return r;
}
__device__ __forceinline__ float sigm_f(float v) {
    return fmaf(tanh_f(v * 0.5f), 0.5f, 0.5f);
}

__global__ void __launch_bounds__(256, 1)
lstm_fused_kernel(const __half* __restrict__ whh0,
                  const __half* __restrict__ whh1,
                  const __half* __restrict__ wih1,
                  const __half* __restrict__ wih0,
                  const float* __restrict__ bih0,
                  const float* __restrict__ bhh0,
                  const float* __restrict__ bih1,
                  const float* __restrict__ bhh1,
                  float* __restrict__ hfin)          // final fp32 h1
{
    extern __shared__ char sm[];
    const uint32_t sb = smem_u32(sm);
    float* red0 = (float*)(sm + LSM_RED0);
    float* red1 = (float*)(sm + LSM_RED1);
    __half* hout0 = (__half*)(sm + LSM_HOUT0);
    __half* hout1 = (__half*)(sm + LSM_HOUT1);
    const uint32_t mbLo = sb + LSM_MBLO;
    const uint32_t mbHi = sb + LSM_MBHI;

    const int tid  = threadIdx.x;
    const int lane = tid & 31;
    const int wid  = tid >> 5;
    const int grp  = blockIdx.x & 3;
    const int jt   = blockIdx.x >> 2;
    const int b0   = grp * 32;
    const int j0   = jt * 16;
    unsigned int* bar    = g_bar + grp * 32;
    unsigned int* myflag = &g_flags[(grp * 32 + jt) * 32];

    const int mf = wid & 3;              // gate
    const int kh = wid >> 2;             // k-half
    const int a_row = mf * 16 + (lane & 7) + ((lane >> 3) & 1) * 8;
    const int a_kb  = (lane >> 4) * 16;
    const int b_row = (lane & 7) + ((lane >> 4) & 1) * 8;
    const int b_kb  = ((lane >> 3) & 1) * 16;

    // publish addressing constants (pre-swizzled group block)
    const uint32_t cbase = (uint32_t)(j0 >> 6) * 4096;
    const int cc0 = (j0 >> 3) & 7;

    // ---- stage Whh0 -> LSM_W0, Whh1 -> LSM_W1, Wih1 -> temp (LSM_H0+H1, 64 KB) ----
    #pragma unroll
    for (int i = 0; i < 16; ++i) {
        int id = tid + i * 256;           // 0..4095 16B-chunks
        int m  = id >> 6, ch = id & 63;
        int g = m >> 4, jl = m & 15;
        size_t roff = ((size_t)(g * H_ + j0 + jl)) * H_ + ch * 8;
        int c = ch >> 3, cc = ch & 7;
        uint32_t soff = c * 8192 + SWZ128((uint32_t)(m * 128 + cc * 16));
        *(uint4*)(sm + LSM_W0 + soff) = *(const uint4*)(whh0 + roff);
        *(uint4*)(sm + LSM_W1 + soff) = *(const uint4*)(whh1 + roff);
        *(uint4*)(sm + LSM_H0 + soff) = *(const uint4*)(wih1 + roff);
    }

    // ---- zero edge h buffers; reset flag; init mbarriers ----
    if (tid < 64) {
        int bl = tid >> 1, p = tid & 1;
        size_t o = (size_t)(b0 + bl) * H_ + j0 + p * 8;
        *(uint4*)&g_h0b[o] = make_uint4(0, 0, 0, 0);
        *(uint4*)&g_h1b[o] = make_uint4(0, 0, 0, 0);
    }
    if (tid == 0) {
        *myflag = 0;
        MBARRIER_INIT(mbLo, 1u);
        MBARRIER_INIT(mbHi, 1u);
    }
    __syncthreads();

    // ---- Wih1 A-fragments -> registers ----
    uint32_t wi1f[64];
    #pragma unroll
    for (int kf = 0; kf < 16; ++kf) {
        int kfa = kh * 16 + kf;
        int c = kfa >> 2, ks = kfa & 3;
        ldsm_x4(&wi1f[kf * 4],
                sb + LSM_H0 + c * 8192 + SWZ128((uint32_t)(a_row * 128 + ks * 32 + a_kb)));
    }
    __syncthreads();   // wi1f loaded everywhere before H0 overwrite

    // ---- stage Wih0 (64 rows x 128 d fp16, 16 KB) into H0; frags -> registers ----
    #pragma unroll
    for (int i = 0; i < 4; ++i) {
        int id = tid + i * 256;           // 0..1023 16B-chunks
        int m  = id >> 4, ch = id & 15;
        int g = m >> 4, jl = m & 15;
        size_t roff = ((size_t)(g * H_ + j0 + jl)) * DIN_ + ch * 8;
        int c = ch >> 3, cc = ch & 7;
        uint32_t soff = c * 8192 + SWZ128((uint32_t)(m * 128 + cc * 16));
        *(uint4*)(sm + LSM_H0 + soff) = *(const uint4*)(wih0 + roff);
    }
    __syncthreads();
    uint32_t wi0f[16];
    #pragma unroll
    for (int kf = 0; kf < 4; ++kf) {
        int kfa = kh * 4 + kf;
        int c = kfa >> 2, ks = kfa & 3;
        ldsm_x4(&wi0f[kf * 4],
                sb + LSM_H0 + c * 8192 + SWZ128((uint32_t)(a_row * 128 + ks * 32 + a_kb)));
    }

    const int m_lo = lane >> 2;
    float bias0_lo = __ldg(&bih0[mf * H_ + j0 + m_lo])     + __ldg(&bhh0[mf * H_ + j0 + m_lo]);
    float bias0_hi = __ldg(&bih0[mf * H_ + j0 + m_lo + 8]) + __ldg(&bhh0[mf * H_ + j0 + m_lo + 8]);
    float bias1_lo = __ldg(&bih1[mf * H_ + j0 + m_lo])     + __ldg(&bhh1[mf * H_ + j0 + m_lo]);
    float bias1_hi = __ldg(&bih1[mf * H_ + j0 + m_lo + 8]) + __ldg(&bhh1[mf * H_ + j0 + m_lo + 8]);

    group_barrier(bar);   // setup complete

    // x staging into red0 area (hi 8 KB + lo 8 KB), chunked-SW128
    auto stage_x = [&](int tt) {
        #pragma unroll
        for (int i = 0; i < 4; ++i) {
            int id  = tid + i * 256;          // 0..1023
            int hl  = id >> 9;
            int rem = id & 511;
            int bl  = rem >> 4, ch = rem & 15;
            const __half* src = (hl ? g_xtl : g_xth)
                + ((size_t)tt * B_ + b0 + bl) * DIN_ + ch * 8;
            int c = ch >> 3, cc = ch & 7;
            uint32_t dst = sb + LSM_RED0 + hl * 8192 + c * 4096
                         + SWZ128((uint32_t)(bl * 128 + cc * 16));
            CPASYNC16(dst, src);
        }
        CPCOMMIT();
    };

    // ---- initial: x[0] prefetch + TMA for t=0 ----
    stage_x(0);
    if (tid == 0) {
        const char* s0 = (const char*)(g_h0b + (size_t)b0 * H_);
        const char* s1 = (const char*)(g_h1a + (size_t)b0 * H_);   // t=0 h1 input unused
        MBARRIER_EXPECT_TX(mbLo, 32768u);
        TMA_BULK_G2S(sb + LSM_H0,         s0,         16384u, mbLo);
        TMA_BULK_G2S(sb + LSM_H1,         s1,         16384u, mbLo);
        MBARRIER_EXPECT_TX(mbHi, 32768u);
        TMA_BULK_G2S(sb + LSM_H0 + 16384, s0 + 16384, 16384u, mbHi);
        TMA_BULK_G2S(sb + LSM_H1 + 16384, s1 + 16384, 16384u, mbHi);
    }

    const int eb = tid & 31;
    const int ej = tid >> 5;
    float c0a = 0.f, c0b = 0.f;   // layer-0 cell states
    float c1a = 0.f, c1b = 0.f;   // layer-1 cell states

    for (int t = 0; t <= T_; ++t) {
        __half* w0 = (t & 1) ? g_h0b : g_h0a;   // h0[t] destination
        __half* w1 = (t & 1) ? g_h1a : g_h1b;   // h1[t-1] destination

        // ---- acc init from biases (kh=0 only) ----
        float acc0[4][4], acc1[4][4];
        #pragma unroll
        for (int nf = 0; nf < 4; ++nf)
            #pragma unroll
            for (int q = 0; q < 4; ++q) {
                acc0[nf][q] = (kh == 0) ? ((q & 2) ? bias0_hi : bias0_lo) : 0.f;
                acc1[nf][q] = (kh == 0) ? ((q & 2) ? bias1_hi : bias1_lo) : 0.f;
            }

        // ---- x-MMA: acc0 += Wih0@(xh + xl)  (x prefetched into red0 area) ----
        if (t < T_) {
            CPWAIT0();
            __syncthreads();     // S_x: all x chunks visible
            #pragma unroll
            for (int kf = 0; kf < 4; ++kf) {
                int kfa = kh * 4 + kf;
                int c = kfa >> 2, ks = kfa & 3;
                uint32_t xh[8], xl[8];
                #pragma unroll
                for (int nfp = 0; nfp < 2; ++nfp) {
                    uint32_t bo = SWZ128((uint32_t)((nfp * 16 + b_row) * 128
                                                     + ks * 32 + b_kb));
                    ldsm_x4(xh + nfp * 4, sb + LSM_RED0        + c * 4096 + bo);
                    ldsm_x4(xl + nfp * 4, sb + LSM_RED0 + 8192 + c * 4096 + bo);
                }
                #pragma unroll
                for (int nf = 0; nf < 4; ++nf) {
                    mma16816(acc0[nf], &wi0f[kf * 4], xh + nf * 2);
                    mma16816(acc0[nf], &wi0f[kf * 4], xl + nf * 2);
                }
            }
            __syncthreads();     // S_x2: x reads done before red0 exchange writes
        }

        // ---- wait own h k-half, then main MMA ----
        mbar_wait(kh == 0 ? mbLo : mbHi, (uint32_t)(t & 1));

        #pragma unroll
        for (int kf = 0; kf < 16; ++kf) {
            int kfa = kh * 16 + kf;
            int c = kfa >> 2, ks = kfa & 3;
            uint32_t a0[4], a1[4], b0f[8], b1f[8];
            uint32_t arow = SWZ128((uint32_t)(a_row * 128 + ks * 32 + a_kb));
            ldsm_x4(a0, sb + LSM_W0 + c * 8192 + arow);
            ldsm_x4(a1, sb + LSM_W1 + c * 8192 + arow);
            #pragma unroll
            for (int nfp = 0; nfp < 2; ++nfp) {
                uint32_t bo = SWZ128((uint32_t)((nfp * 16 + b_row) * 128 + ks * 32 + b_kb));
                ldsm_x4(b0f + nfp * 4, sb + LSM_H0 + c * 4096 + bo);
                ldsm_x4(b1f + nfp * 4, sb + LSM_H1 + c * 4096 + bo);
            }
            #pragma unroll
            for (int nf = 0; nf < 4; ++nf) {
                mma16816(acc0[nf], a0, b0f + nf * 2);
                mma16816(acc1[nf], &wi1f[kf * 4], b0f + nf * 2);
                mma16816(acc1[nf], a1, b1f + nf * 2);
            }
        }

        // ---- exchange partials: both layers, ONE sync ----
        #pragma unroll
        for (int nf = 0; nf < 4; ++nf)
            #pragma unroll
            for (int q = 0; q < 4; ++q) {
                int m = (lane >> 2) + 8 * (q >> 1);
                int n = nf * 8 + 2 * (lane & 3) + (q & 1);
                int idx = ((kh * 4 + mf) * 16 + m) * 33 + n;
                red0[idx] = acc0[nf][q];
                red1[idx] = acc1[nf][q];
            }
        __syncthreads();

        // ---- epilogues: compute, gather into smem hout (H0 tail is dead here) ----
        if (t < T_) {
            #pragma unroll
            for (int cell = 0; cell < 2; ++cell) {
                int jl = ej + cell * 8;
                float pre[4];
                #pragma unroll
                for (int g = 0; g < 4; ++g)
                    pre[g] = red0[(g * 16 + jl) * 33 + eb]
                           + red0[((4 + g) * 16 + jl) * 33 + eb];
                float ii = sigm_f(pre[0]), ff = sigm_f(pre[1]);
                float gg = tanh_f(pre[2]), oo = sigm_f(pre[3]);
                float& cc = cell ? c0b : c0a;
                cc = ff * cc + ii * gg;
                hout0[eb * 16 + cell * 8 + ej] = __float2half(oo * tanh_f(cc));
            }
        }
        if (t >= 1) {
            #pragma unroll
            for (int cell = 0; cell < 2; ++cell) {
                int jl = ej + cell * 8;
                float pre[4];
                #pragma unroll
                for (int g = 0; g < 4; ++g)
                    pre[g] = red1[(g * 16 + jl) * 33 + eb]
                           + red1[((4 + g) * 16 + jl) * 33 + eb];
                float ii = sigm_f(pre[0]), ff = sigm_f(pre[1]);
                float gg = tanh_f(pre[2]), oo = sigm_f(pre[3]);
                float& cc = cell ? c1b : c1a;
                cc = ff * cc + ii * gg;
                float hv = oo * tanh_f(cc);
                hout1[eb * 16 + cell * 8 + ej] = __float2half(hv);
                if (t == T_)
                    hfin[(size_t)(b0 + eb) * H_ + j0 + jl] = hv;
            }
        }

        // ---- coalesced publish + barrier window ----
        if (t < T_) {
            __syncthreads();                       // hout complete
            if (tid < 128) {                       // 16B stores: 128 L2 transactions
                int buf = tid >> 6;
                int idx = tid & 63;
                int ebp = idx >> 1, q = idx & 1;
                if (buf == 0 || t >= 1) {
                    const __half* hsrc = buf ? hout1 : hout0;
                    uint4 v = *(const uint4*)(hsrc + ebp * 16 + q * 8);
                    char* basep = (char*)((buf ? w1 : w0) + (size_t)b0 * H_);
                    uint32_t off = cbase
                        + SWZ128((uint32_t)(ebp * 128 + (cc0 + q) * 16));
                    *(uint4*)(basep + off) = v;
                }
            }
            const unsigned int gen = (unsigned int)(t + 1);
            __syncthreads();                       // STGs ordered before fence
            if (tid == 0) {
                __threadfence();                   // h stores visible gpu-wide
                asm volatile("st.relaxed.gpu.u32 [%0], %1;"
                             :: "l"(myflag), "r"(gen) : "memory");
            }
            if (t + 1 < T_) stage_x(t + 1);        // overlaps with the poll below
            if (wid == 0) {                        // 32 lanes poll 32 producers
                unsigned int* fp = &g_flags[(grp * 32 + lane) * 32];
                unsigned int v;
                do {
                    asm volatile("ld.acquire.gpu.u32 %0, [%1];"
                                 : "=r"(v) : "l"(fp) : "memory");
                } while (__any_sync(0xffffffffu, v < gen));
                if (lane == 0) {                   // issue next h TMA on detect
                    const char* s0 = (const char*)(w0 + (size_t)b0 * H_);
                    const char* s1 = (const char*)(w1 + (size_t)b0 * H_);
                    MBARRIER_EXPECT_TX(mbLo, 32768u);
                    TMA_BULK_G2S(sb + LSM_H0,         s0,         16384u, mbLo);
                    TMA_BULK_G2S(sb + LSM_H1,         s1,         16384u, mbLo);
                    MBARRIER_EXPECT_TX(mbHi, 32768u);
                    TMA_BULK_G2S(sb + LSM_H0 + 16384, s0 + 16384, 16384u, mbHi);
                    TMA_BULK_G2S(sb + LSM_H1 + 16384, s1 + 16384, 16384u, mbHi);
                }
            }
            __syncthreads();
        }
    }
}

// ---------------- fc head -----------------------------------------------------------
__global__ void fc_kernel(const float* __restrict__ h,
                          const float* __restrict__ W,
                          const float* __restrict__ bias,
                          float* __restrict__ out)
{
    int tid = threadIdx.x;
    int b = tid >> 1, o = tid & 1;
    float s = bias[o];
    const float* hp = h + (size_t)b * H_;
    const float* wp = W + (size_t)o * H_;
    for (int k = 0; k < H_; ++k) s = fmaf(hp[k], wp[k], s);
    out[b * OUT_ + o] = s;
}

// ---------------- launch -------------------------------------------------------------
extern "C" void kernel_launch(void* const* d_in, const int* in_sizes, int n_in,
                              void* d_out, int out_size)
{
    const float* x    = (const float*)d_in[0];
    const float* Wih0 = (const float*)d_in[1];
    const float* Whh0 = (const float*)d_in[2];
    const float* bih0 = (const float*)d_in[3];
    const float* bhh0 = (const float*)d_in[4];
    const float* Wih1 = (const float*)d_in[5];
    const float* Whh1 = (const float*)d_in[6];
    const float* bih1 = (const float*)d_in[7];
    const float* bhh1 = (const float*)d_in[8];
    const float* fcW  = (const float*)d_in[9];
    const float* fcb  = (const float*)d_in[10];
    float* out = (float*)d_out;

    float* hA;
    __half *wi0, *wr0, *wr1, *wi1;
    cudaGetSymbolAddress((void**)&hA,  g_hA);
    cudaGetSymbolAddress((void**)&wi0, g_wi0);
    cudaGetSymbolAddress((void**)&wr0, g_wr0);
    cudaGetSymbolAddress((void**)&wr1, g_wr1);
    cudaGetSymbolAddress((void**)&wi1, g_wi1);

    cudaFuncSetAttribute(lstm_fused_kernel,
                         cudaFuncAttributeMaxDynamicSharedMemorySize, LSM_TOTAL);

    // 1) transpose x -> fp16 hi/lo xt[t][b][d]
    transpose_kernel<<<dim3(T_ / 32, DIN_ / 32, B_), dim3(32, 8)>>>(x);

    // 2) weight prep (all single fp16)
    wconv3_kernel<<<dim3((G4H_ * H_ + 255) / 256, 3), 256>>>(
        Whh0, wr0, Whh1, wr1, Wih1, wi1, G4H_ * H_);
    wconv1_kernel<<<(G4H_ * DIN_ + 255) / 256, 256>>>(Wih0, wi0, G4H_ * DIN_);

    // 3) fully-fused dual-layer recurrence (coalesced publish)
    lstm_fused_kernel<<<128, 256, LSM_TOTAL>>>(wr0, wr1, wi1, wi0,
                                               bih0, bhh0, bih1, bhh1, hA);

    // 4) fc head
    fc_kernel<<<1, 256>>>(hA, fcW, fcb, out);
}